// round 1
// baseline (speedup 1.0000x reference)
#include <cuda_runtime.h>
#include <math.h>

// ---------------- problem constants ----------------
constexpr int BATCH = 8;
constexpr int HWP   = 224;            // H = W = 224, pad = 0 (224 % 7 == 0)
constexpr int LPIX  = HWP * HWP;      // 50176
constexpr int DIM   = 192;
constexpr int NH    = 6;
constexpr int HD    = 32;
constexpr int DFF   = 768;
constexpr int WSZ   = 7;
constexpr int SHF   = 3;
constexpr int NTOK  = 49;             // tokens per window
constexpr int NWIN  = 1024;           // windows per batch image (32*32)
constexpr int NWTOT = BATCH * NWIN;   // 8192
constexpr int MTOK  = BATCH * LPIX;   // 401408 total tokens

// ---------------- scratch (device globals; no allocations allowed) -------
// g_h doubles as: (a) LN1 output in window order (first MTOK*DIM floats),
//                 (b) MLP hidden (MTOK*DFF floats)   -- lifetimes disjoint.
// g_att doubles as: (a) attention output, (b) LN2 output -- disjoint.
__device__ float g_qkv[(size_t)MTOK * 3 * DIM];   // [m][576], window-token order
__device__ float g_att[(size_t)MTOK * DIM];
__device__ float g_y  [(size_t)MTOK * DIM];       // residual stream after attn
__device__ float g_h  [(size_t)MTOK * DFF];

// ---------------- f32x2 helpers (FFMA2: 2x FFMA issue rate on sm_103a) ---
__device__ __forceinline__ unsigned long long pk2(float x, float y) {
    unsigned long long r;
    asm("mov.b64 %0, {%1,%2};" : "=l"(r) : "f"(x), "f"(y));
    return r;
}
__device__ __forceinline__ void fma2(unsigned long long& d,
                                     unsigned long long a, unsigned long long b) {
    asm("fma.rn.f32x2 %0, %1, %2, %0;" : "+l"(d) : "l"(a), "l"(b));
}

// ---------------- LayerNorm (one warp per token row) ----------------
// PHASE 0: in = x (b,pos,c), gather through roll(-3)+window partition,
//          write window-ordered tokens to g_h.
// PHASE 1: in = g_y (token order), write to g_att.
template <int PHASE>
__global__ void __launch_bounds__(256) k_ln(const float* __restrict__ xin,
                                            const float* __restrict__ w,
                                            const float* __restrict__ b) {
    int warp = threadIdx.x >> 5, lane = threadIdx.x & 31;
    int m = blockIdx.x * 8 + warp;           // output token index
    const float* src;
    float* dst;
    if (PHASE == 0) {
        int bw = m / NTOK, n = m - bw * NTOK;
        int bb = bw >> 10, wdx = bw & 1023;
        int wi = wdx >> 5, wj = wdx & 31;
        int r = n / WSZ, c = n - r * WSZ;
        int pi = wi * WSZ + r + SHF; if (pi >= HWP) pi -= HWP;
        int pj = wj * WSZ + c + SHF; if (pj >= HWP) pj -= HWP;
        src = xin + ((size_t)bb * LPIX + (size_t)pi * HWP + pj) * DIM;
        dst = g_h + (size_t)m * DIM;
    } else {
        src = g_y + (size_t)m * DIM;
        dst = g_att + (size_t)m * DIM;
    }
    float v[6]; float s = 0.f, s2 = 0.f;
#pragma unroll
    for (int j = 0; j < 6; j++) {
        v[j] = src[lane + 32 * j];
        s += v[j]; s2 += v[j] * v[j];
    }
#pragma unroll
    for (int o = 16; o > 0; o >>= 1) {
        s  += __shfl_xor_sync(0xffffffffu, s,  o);
        s2 += __shfl_xor_sync(0xffffffffu, s2, o);
    }
    float mu  = s * (1.f / DIM);
    float var = s2 * (1.f / DIM) - mu * mu;
    float rs  = rsqrtf(var + 1e-5f);
#pragma unroll
    for (int j = 0; j < 6; j++) {
        int kk = lane + 32 * j;
        dst[kk] = (v[j] - mu) * rs * __ldg(&w[kk]) + __ldg(&b[kk]);
    }
}

// ---------------- generic tiled fp32 GEMM with per-mode epilogue ---------
// C[m, col] = sum_k A[m,k] * W[k,col]   (A chosen by MODE from scratch)
// MODE 0: A=g_h (LN1 out), out -> g_qkv[m*576+col]           (+qkv_b)
// MODE 1: A=g_att (attn out), out -> g_y[scatter]+x residual (+proj_b)
// MODE 2: A=g_att (LN2 out), out -> gelu -> g_h[m*768+col]   (+b1)
// MODE 3: A=g_h (hidden),   out -> d_out = g_y + acc         (+b2)
constexpr int BM = 64, BN = 64, BK = 32, ASTR = 66;

template <int MODE, int K, int NW>
__global__ void __launch_bounds__(256) k_gemm(const float* __restrict__ W,
                                              const float* __restrict__ bias,
                                              const float* __restrict__ aux,
                                              float* __restrict__ dout) {
    __shared__ __align__(16) float As[BK * ASTR];   // [k][m], padded stride 66
    __shared__ __align__(16) float Bs[BK * BN];     // [k][n]

    const float* A;
    if      (MODE == 0) A = g_h;
    else if (MODE == 1) A = g_att;
    else if (MODE == 2) A = g_att;
    else                A = g_h;

    const int m0 = blockIdx.x * BM, n0 = blockIdx.y * BN;
    const int t = threadIdx.x;
    const int tx = t & 15, ty = t >> 4;
    const int row0 = ty * 4, col0 = tx * 4;

    unsigned long long acc[2][4];
#pragma unroll
    for (int p = 0; p < 2; p++)
#pragma unroll
        for (int j = 0; j < 4; j++) acc[p][j] = 0ull;

    for (int k0 = 0; k0 < K; k0 += BK) {
        // stage A tile transposed: As[k][m]
#pragma unroll
        for (int it = 0; it < 2; it++) {
            int id = t + it * 256;          // 512 float4 = 64 rows x 8
            int r = id >> 3, f = id & 7;
            float4 va = *(const float4*)(A + (size_t)(m0 + r) * K + k0 + f * 4);
            As[(f * 4 + 0) * ASTR + r] = va.x;
            As[(f * 4 + 1) * ASTR + r] = va.y;
            As[(f * 4 + 2) * ASTR + r] = va.z;
            As[(f * 4 + 3) * ASTR + r] = va.w;
        }
        // stage B tile: Bs[k][n]
#pragma unroll
        for (int it = 0; it < 2; it++) {
            int id = t + it * 256;          // 512 float4 = 32 k x 16
            int kk = id >> 4, f = id & 15;
            *(float4*)(Bs + kk * BN + f * 4) =
                *(const float4*)(W + (size_t)(k0 + kk) * NW + n0 + f * 4);
        }
        __syncthreads();
#pragma unroll
        for (int kk = 0; kk < BK; kk++) {
            unsigned long long a0 = *(const unsigned long long*)(As + kk * ASTR + row0);
            unsigned long long a1 = *(const unsigned long long*)(As + kk * ASTR + row0 + 2);
            float4 bq = *(const float4*)(Bs + kk * BN + col0);
            unsigned long long b0 = pk2(bq.x, bq.x), b1 = pk2(bq.y, bq.y);
            unsigned long long b2 = pk2(bq.z, bq.z), b3 = pk2(bq.w, bq.w);
            fma2(acc[0][0], a0, b0); fma2(acc[0][1], a0, b1);
            fma2(acc[0][2], a0, b2); fma2(acc[0][3], a0, b3);
            fma2(acc[1][0], a1, b0); fma2(acc[1][1], a1, b1);
            fma2(acc[1][2], a1, b2); fma2(acc[1][3], a1, b3);
        }
        __syncthreads();
    }

    float o[4][4];
#pragma unroll
    for (int p = 0; p < 2; p++)
#pragma unroll
        for (int j = 0; j < 4; j++) {
            float lo, hi;
            asm("mov.b64 {%0,%1}, %2;" : "=f"(lo), "=f"(hi) : "l"(acc[p][j]));
            o[p * 2][j] = lo; o[p * 2 + 1][j] = hi;
        }

#pragma unroll
    for (int i = 0; i < 4; i++) {
#pragma unroll
        for (int j = 0; j < 4; j++) {
            int m = m0 + row0 + i;
            int col = n0 + col0 + j;
            float v = o[i][j] + __ldg(&bias[col]);
            if (MODE == 0) {
                g_qkv[(size_t)m * (3 * DIM) + col] = v;
            } else if (MODE == 1) {
                // reverse window partition + roll(+3), add residual x
                int bw = m / NTOK, n = m - bw * NTOK;
                int bb = bw >> 10, wdx = bw & 1023;
                int wi = wdx >> 5, wj = wdx & 31;
                int r = n / WSZ, c = n - r * WSZ;
                int pi = wi * WSZ + r + SHF; if (pi >= HWP) pi -= HWP;
                int pj = wj * WSZ + c + SHF; if (pj >= HWP) pj -= HWP;
                size_t dst = ((size_t)bb * LPIX + (size_t)pi * HWP + pj) * DIM + col;
                g_y[dst] = aux[dst] + v;        // aux = original x
            } else if (MODE == 2) {
                v = 0.5f * v * (1.f + erff(v * 0.70710678118654752f));  // exact gelu
                g_h[(size_t)m * DFF + col] = v;
            } else {
                dout[(size_t)m * DIM + col] = g_y[(size_t)m * DIM + col] + v;
            }
        }
    }
}

// ---------------- windowed attention: one block per (window, head) -------
__global__ void __launch_bounds__(128) k_attn(const float* __restrict__ rpb) {
    __shared__ float qs[NTOK][33], ks[NTOK][33], vs[NTOK][33];
    __shared__ float sc[NTOK][50];

    const int bw = blockIdx.x;             // 0..8191
    const int h  = blockIdx.y;             // 0..5
    const int wdx = bw & 1023;
    const int wi = wdx >> 5, wj = wdx & 31;
    const int t = threadIdx.x;

    const float* gq = g_qkv + (size_t)bw * NTOK * (3 * DIM) + h * HD;
    for (int e = t; e < NTOK * HD; e += 128) {
        int n = e >> 5, d = e & 31;
        const float* row = gq + (size_t)n * (3 * DIM);
        qs[n][d] = row[d];
        ks[n][d] = row[DIM + d];
        vs[n][d] = row[2 * DIM + d];
    }
    __syncthreads();

    const float scale = 0.17677669529663687f;   // 32^-0.5
    for (int e = t; e < NTOK * NTOK; e += 128) {
        int nq = e / NTOK, mk = e - nq * NTOK;
        float s = 0.f;
#pragma unroll
        for (int d = 0; d < HD; d++) s += qs[nq][d] * ks[mk][d];
        s *= scale;
        int r1 = nq / WSZ, c1 = nq - r1 * WSZ;
        int r2 = mk / WSZ, c2 = mk - r2 * WSZ;
        s += __ldg(&rpb[((r1 - r2 + 6) * 13 + (c1 - c2 + 6)) * NH + h]);
        // shift mask (rolled-coordinate region ids; boundaries 217/221)
        int i1 = wi * WSZ + r1, i2 = wi * WSZ + r2;
        int j1 = wj * WSZ + c1, j2 = wj * WSZ + c2;
        int h1 = (i1 < HWP - WSZ) ? 0 : ((i1 < HWP - SHF) ? 1 : 2);
        int h2 = (i2 < HWP - WSZ) ? 0 : ((i2 < HWP - SHF) ? 1 : 2);
        int g1 = (j1 < HWP - WSZ) ? 0 : ((j1 < HWP - SHF) ? 1 : 2);
        int g2 = (j2 < HWP - WSZ) ? 0 : ((j2 < HWP - SHF) ? 1 : 2);
        if (h1 != h2 || g1 != g2) s -= 100.f;
        sc[nq][mk] = s;
    }
    __syncthreads();

    if (t < NTOK) {
        float mx = -1e30f;
        for (int j = 0; j < NTOK; j++) mx = fmaxf(mx, sc[t][j]);
        float sum = 0.f;
        for (int j = 0; j < NTOK; j++) {
            float e = __expf(sc[t][j] - mx);
            sc[t][j] = e; sum += e;
        }
        float inv = 1.f / sum;
        for (int j = 0; j < NTOK; j++) sc[t][j] *= inv;
    }
    __syncthreads();

    for (int e = t; e < NTOK * HD; e += 128) {
        int nq = e >> 5, d = e & 31;
        float s = 0.f;
#pragma unroll
        for (int mm = 0; mm < NTOK; mm++) s += sc[nq][mm] * vs[mm][d];
        int m = bw * NTOK + nq;
        g_att[(size_t)m * DIM + h * HD + d] = s;
    }
}

// ---------------- launcher ----------------
extern "C" void kernel_launch(void* const* d_in, const int* in_sizes, int n_in,
                              void* d_out, int out_size) {
    // metadata order: x, H, W, qkv_w, qkv_b, proj_w, proj_b, rpb,
    //                 n1w, n1b, n2w, n2b, w1, b1, w2, b2
    // Be robust to H/W scalars possibly being dropped from the input list.
    int base = (n_in >= 16) ? 3 : 1;
    const float* x      = (const float*)d_in[0];
    const float* qkv_w  = (const float*)d_in[base + 0];
    const float* qkv_b  = (const float*)d_in[base + 1];
    const float* proj_w = (const float*)d_in[base + 2];
    const float* proj_b = (const float*)d_in[base + 3];
    const float* rpb    = (const float*)d_in[base + 4];
    const float* n1w    = (const float*)d_in[base + 5];
    const float* n1b    = (const float*)d_in[base + 6];
    const float* n2w    = (const float*)d_in[base + 7];
    const float* n2b    = (const float*)d_in[base + 8];
    const float* w1     = (const float*)d_in[base + 9];
    const float* b1     = (const float*)d_in[base + 10];
    const float* w2     = (const float*)d_in[base + 11];
    const float* b2     = (const float*)d_in[base + 12];
    float* out = (float*)d_out;

    const int nblk_ln = MTOK / 8;      // 50176
    const int mt = MTOK / BM;          // 6272

    // 1. LN1 + shifted-window gather -> g_h (window-token order)
    k_ln<0><<<nblk_ln, 256>>>(x, n1w, n1b);
    // 2. QKV GEMM -> g_qkv
    k_gemm<0, DIM, 3 * DIM><<<dim3(mt, (3 * DIM) / BN), 256>>>(qkv_w, qkv_b, nullptr, nullptr);
    // 3. window attention -> g_att
    k_attn<<<dim3(NWTOT, NH), 128>>>(rpb);
    // 4. proj GEMM + reverse roll scatter + residual -> g_y
    k_gemm<1, DIM, DIM><<<dim3(mt, DIM / BN), 256>>>(proj_w, proj_b, x, nullptr);
    // 5. LN2 -> g_att (reuse)
    k_ln<1><<<nblk_ln, 256>>>(x, n2w, n2b);
    // 6. MLP1 + exact GELU -> g_h (reuse)
    k_gemm<2, DIM, DFF><<<dim3(mt, DFF / BN), 256>>>(w1, b1, nullptr, nullptr);
    // 7. MLP2 + residual -> d_out
    k_gemm<3, DFF, DIM><<<dim3(mt, DIM / BN), 256>>>(w2, b2, nullptr, out);
}

// round 4
// speedup vs baseline: 1.6967x; 1.6967x over previous
#include <cuda_runtime.h>
#include <stdint.h>
#include <math.h>

using u32 = unsigned int;

// ---------------- problem constants ----------------
constexpr int BATCH = 8;
constexpr int HWP   = 224;
constexpr int LPIX  = HWP * HWP;      // 50176
constexpr int DIM   = 192;
constexpr int NH    = 6;
constexpr int HD    = 32;
constexpr int DFF   = 768;
constexpr int WSZ   = 7;
constexpr int SHF   = 3;
constexpr int NTOK  = 49;
constexpr int NWTOT = 8192;
constexpr int MTOK  = BATCH * LPIX;   // 401408

// ---------------- scratch globals ----------------
__device__ float g_qkv[(size_t)MTOK * 3 * DIM];
__device__ float g_att[(size_t)MTOK * DIM];
__device__ float g_y  [(size_t)MTOK * DIM];
__device__ float g_h  [(size_t)MTOK * DFF];
__device__ float g_wt [442368];               // transposed weights (tf32-rounded)

constexpr int WT_QKV = 0;        // [576][192]
constexpr int WT_PRJ = 110592;   // [192][192]
constexpr int WT_M1  = 147456;   // [768][192]
constexpr int WT_M2  = 294912;   // [192][768]

// ---------------- helpers ----------------
__device__ __forceinline__ float to_tf32(float x) {
    float r; asm("cvt.rna.tf32.f32 %0, %1;" : "=f"(r) : "f"(x)); return r;
}
__device__ __forceinline__ void mma8(float* c, const u32* a, const u32* b) {
    asm volatile(
        "mma.sync.aligned.m16n8k8.row.col.f32.tf32.tf32.f32 "
        "{%0,%1,%2,%3}, {%4,%5,%6,%7}, {%8,%9}, {%0,%1,%2,%3};"
        : "+f"(c[0]), "+f"(c[1]), "+f"(c[2]), "+f"(c[3])
        : "r"(a[0]), "r"(a[1]), "r"(a[2]), "r"(a[3]), "r"(b[0]), "r"(b[1]));
}
// reverse window-partition + roll(+3): window-order token m -> pixel row base
__device__ __forceinline__ size_t scat_row(int m) {
    int bw = m / NTOK, n = m - bw * NTOK;
    int bb = bw >> 10, wdx = bw & 1023;
    int wi = wdx >> 5, wj = wdx & 31;
    int r = n / WSZ, cc = n - r * WSZ;
    int pi = wi * WSZ + r + SHF; if (pi >= HWP) pi -= HWP;
    int pj = wj * WSZ + cc + SHF; if (pj >= HWP) pj -= HWP;
    return ((size_t)bb * LPIX + (size_t)pi * HWP + pj) * DIM;
}

// ---------------- weight transpose (+ tf32 rounding) ----------------
__global__ void k_tr(const float* __restrict__ W, float* __restrict__ WT, int K, int N) {
    int i = blockIdx.x * 256 + threadIdx.x;
    if (i < K * N) {
        int k = i / N, n = i - k * N;
        WT[(size_t)n * K + k] = to_tf32(W[i]);
    }
}

// ---------------- LayerNorm (one warp / token), outputs tf32-rounded ------
template <int PHASE>
__global__ void __launch_bounds__(256) k_ln(const float* __restrict__ xin,
                                            const float* __restrict__ w,
                                            const float* __restrict__ b) {
    int warp = threadIdx.x >> 5, lane = threadIdx.x & 31;
    int m = blockIdx.x * 8 + warp;
    const float* src;
    float* dst;
    if (PHASE == 0) {
        int bw = m / NTOK, n = m - bw * NTOK;
        int bb = bw >> 10, wdx = bw & 1023;
        int wi = wdx >> 5, wj = wdx & 31;
        int r = n / WSZ, c = n - r * WSZ;
        int pi = wi * WSZ + r + SHF; if (pi >= HWP) pi -= HWP;
        int pj = wj * WSZ + c + SHF; if (pj >= HWP) pj -= HWP;
        src = xin + ((size_t)bb * LPIX + (size_t)pi * HWP + pj) * DIM;
        dst = g_h + (size_t)m * DIM;
    } else {
        src = g_y + (size_t)m * DIM;
        dst = g_att + (size_t)m * DIM;
    }
    float v[6]; float s = 0.f, s2 = 0.f;
#pragma unroll
    for (int j = 0; j < 6; j++) {
        v[j] = src[lane + 32 * j];
        s += v[j]; s2 += v[j] * v[j];
    }
#pragma unroll
    for (int o = 16; o > 0; o >>= 1) {
        s  += __shfl_xor_sync(0xffffffffu, s,  o);
        s2 += __shfl_xor_sync(0xffffffffu, s2, o);
    }
    float mu  = s * (1.f / DIM);
    float var = s2 * (1.f / DIM) - mu * mu;
    float rs  = rsqrtf(var + 1e-5f);
#pragma unroll
    for (int j = 0; j < 6; j++) {
        int kk = lane + 32 * j;
        dst[kk] = to_tf32((v[j] - mu) * rs * __ldg(&w[kk]) + __ldg(&b[kk]));
    }
}

// ---------------- tf32 mma.sync GEMM: C[M,N] = A[M,K] @ W[K,N] -----------
// BM=128, BN=96, K staged 192 at a time (pitch 196 -> conflict-free frags).
// 8 warps in 2x4 grid, warp tile 64x24 (4 m-tiles x 3 n-tiles of m16n8k8).
// MODE 0: A=g_h    -> g_qkv (+qkv_b)
// MODE 1: A=g_att  -> scatter + residual into g_y (+proj_b)
// MODE 2: A=g_att  -> gelu -> g_h (+b1) (tf32-rounded)
// MODE 3: A=g_h    -> d_out = g_y + acc (+b2)
constexpr int PITCH = 196;
constexpr int MMA_SMEM = (128 * PITCH + 96 * PITCH) * 4;   // 175,616 B

template <int MODE, int KTOT>
__global__ void __launch_bounds__(256) k_mma(const float* __restrict__ WT,
                                             const float* __restrict__ bias,
                                             const float* __restrict__ aux,
                                             float* __restrict__ dout) {
    extern __shared__ float sm[];
    float* As = sm;                    // [128][196]
    float* Bs = sm + 128 * PITCH;      // [96][196]

    const int t = threadIdx.x;
    const int n0 = blockIdx.x * 96;
    const int m0 = blockIdx.y * 128;
    const float* A = (MODE == 0 || MODE == 3) ? g_h : g_att;

    const int lane = t & 31, w = t >> 5;
    const int mw = (w >> 2) * 64;      // 0 or 64
    const int nw = (w & 3) * 24;       // 0,24,48,72
    const int g = lane >> 2, tg = lane & 3;

    float acc[4][3][4];
#pragma unroll
    for (int i = 0; i < 4; i++)
#pragma unroll
        for (int j = 0; j < 3; j++)
#pragma unroll
            for (int q = 0; q < 4; q++) acc[i][j][q] = 0.f;

    constexpr int NC = KTOT / 192;
#pragma unroll 1
    for (int c = 0; c < NC; c++) {
        if (c) __syncthreads();
        // stage A: 128 rows x 48 float4
#pragma unroll
        for (int it = 0; it < 24; it++) {
            int id = t + it * 256;
            int row = id / 48, f = id - row * 48;
            float4 v = *(const float4*)(A + (size_t)(m0 + row) * KTOT + c * 192 + f * 4);
            *(float4*)(As + row * PITCH + f * 4) = v;
        }
        // stage B: 96 rows x 48 float4
#pragma unroll
        for (int it = 0; it < 18; it++) {
            int id = t + it * 256;
            int row = id / 48, f = id - row * 48;
            float4 v = *(const float4*)(WT + (size_t)(n0 + row) * KTOT + c * 192 + f * 4);
            *(float4*)(Bs + row * PITCH + f * 4) = v;
        }
        __syncthreads();

#pragma unroll 4
        for (int ks = 0; ks < 24; ks++) {
            int k0 = ks * 8;
            u32 a[4][4], b[3][2];
#pragma unroll
            for (int i = 0; i < 4; i++) {
                const float* p = As + (mw + i * 16 + g) * PITCH + k0 + tg;
                a[i][0] = __float_as_uint(p[0]);
                a[i][1] = __float_as_uint(p[8 * PITCH]);
                a[i][2] = __float_as_uint(p[4]);
                a[i][3] = __float_as_uint(p[8 * PITCH + 4]);
            }
#pragma unroll
            for (int j = 0; j < 3; j++) {
                const float* p = Bs + (nw + j * 8 + g) * PITCH + k0 + tg;
                b[j][0] = __float_as_uint(p[0]);
                b[j][1] = __float_as_uint(p[4]);
            }
#pragma unroll
            for (int i = 0; i < 4; i++)
#pragma unroll
                for (int j = 0; j < 3; j++) mma8(acc[i][j], a[i], b[j]);
        }
    }

    // ---------------- epilogue (register -> global, per MODE) ------------
#pragma unroll
    for (int i = 0; i < 4; i++) {
        int r0 = m0 + mw + i * 16 + g;      // rows r0 and r0+8
#pragma unroll
        for (int half = 0; half < 2; half++) {
            int m = r0 + half * 8;
            size_t srow;
            if (MODE == 1) srow = scat_row(m);
#pragma unroll
            for (int j = 0; j < 3; j++) {
                int col = n0 + nw + j * 8 + 2 * tg;
                float v0 = acc[i][j][half * 2 + 0] + __ldg(&bias[col]);
                float v1 = acc[i][j][half * 2 + 1] + __ldg(&bias[col + 1]);
                if (MODE == 0) {
                    *(float2*)(g_qkv + (size_t)m * 576 + col) = make_float2(v0, v1);
                } else if (MODE == 1) {
                    float2 xr = *(const float2*)(aux + srow + col);
                    *(float2*)(g_y + srow + col) = make_float2(xr.x + v0, xr.y + v1);
                } else if (MODE == 2) {
                    v0 = to_tf32(0.5f * v0 * (1.f + erff(v0 * 0.70710678118654752f)));
                    v1 = to_tf32(0.5f * v1 * (1.f + erff(v1 * 0.70710678118654752f)));
                    *(float2*)(g_h + (size_t)m * DFF + col) = make_float2(v0, v1);
                } else {
                    const float* yy = g_y + (size_t)m * DIM + col;
                    *(float2*)(dout + (size_t)m * DIM + col) =
                        make_float2(yy[0] + v0, yy[1] + v1);
                }
            }
        }
    }
}

// ---------------- windowed attention: thread-per-query, broadcast K/V -----
__global__ void __launch_bounds__(64) k_attn(const float* __restrict__ rpb) {
    __shared__ float qs[NTOK][33];
    __shared__ __align__(16) float ks[NTOK][32];
    __shared__ __align__(16) float vs[NTOK][32];
    __shared__ float bs[169];

    const int bw = blockIdx.x, h = blockIdx.y, t = threadIdx.x;
    const int wdx = bw & 1023, wi = wdx >> 5, wj = wdx & 31;
    const float* base = g_qkv + (size_t)bw * NTOK * 576 + h * HD;

    for (int e = t; e < NTOK * HD; e += 64) {
        int n = e >> 5, d = e & 31;
        qs[n][d] = base[(size_t)n * 576 + d];
    }
    for (int e = t; e < NTOK * 8; e += 64) {
        int n = e >> 3, f = e & 7;
        const float* row = base + (size_t)n * 576;
        *(float4*)(&ks[n][f * 4]) = *(const float4*)(row + DIM + f * 4);
        *(float4*)(&vs[n][f * 4]) = *(const float4*)(row + 2 * DIM + f * 4);
    }
    for (int e = t; e < 169; e += 64) bs[e] = rpb[e * NH + h];
    __syncthreads();

    if (t >= NTOK) return;

    const int r1 = t / WSZ, c1 = t - r1 * WSZ;
    const int i1 = wi * WSZ + r1, j1 = wj * WSZ + c1;
    const int h1 = (i1 < HWP - WSZ) ? 0 : ((i1 < HWP - SHF) ? 1 : 2);
    const int g1 = (j1 < HWP - WSZ) ? 0 : ((j1 < HWP - SHF) ? 1 : 2);
    const float scale = 0.17677669529663687f;

    float q[HD];
#pragma unroll
    for (int d = 0; d < HD; d++) q[d] = qs[t][d];

    float p[NTOK];
#pragma unroll
    for (int mk = 0; mk < NTOK; mk++) {
        float s = 0.f;
#pragma unroll
        for (int f = 0; f < 8; f++) {
            float4 kv = *(const float4*)(&ks[mk][f * 4]);     // broadcast
            s += q[f * 4 + 0] * kv.x + q[f * 4 + 1] * kv.y
               + q[f * 4 + 2] * kv.z + q[f * 4 + 3] * kv.w;
        }
        int r2 = mk / WSZ, c2 = mk - r2 * WSZ;
        s = s * scale + bs[(r1 - r2 + 6) * 13 + (c1 - c2 + 6)];
        int i2 = wi * WSZ + r2, j2 = wj * WSZ + c2;
        int h2 = (i2 < HWP - WSZ) ? 0 : ((i2 < HWP - SHF) ? 1 : 2);
        int g2 = (j2 < HWP - WSZ) ? 0 : ((j2 < HWP - SHF) ? 1 : 2);
        if (h1 != h2 || g1 != g2) s -= 100.f;
        p[mk] = s;
    }

    float mx = -1e30f;
#pragma unroll
    for (int j = 0; j < NTOK; j++) mx = fmaxf(mx, p[j]);
    float sum = 0.f;
#pragma unroll
    for (int j = 0; j < NTOK; j++) { p[j] = __expf(p[j] - mx); sum += p[j]; }
    float inv = 1.f / sum;
#pragma unroll
    for (int j = 0; j < NTOK; j++) p[j] *= inv;

    float o[HD];
#pragma unroll
    for (int d = 0; d < HD; d++) o[d] = 0.f;
#pragma unroll
    for (int mk = 0; mk < NTOK; mk++) {
        float pm = p[mk];
#pragma unroll
        for (int f = 0; f < 8; f++) {
            float4 vv = *(const float4*)(&vs[mk][f * 4]);     // broadcast
            o[f * 4 + 0] += pm * vv.x; o[f * 4 + 1] += pm * vv.y;
            o[f * 4 + 2] += pm * vv.z; o[f * 4 + 3] += pm * vv.w;
        }
    }
    float* dst = g_att + ((size_t)(bw * NTOK + t)) * DIM + h * HD;
#pragma unroll
    for (int f = 0; f < 8; f++) {
        *(float4*)(dst + f * 4) = make_float4(to_tf32(o[f * 4 + 0]), to_tf32(o[f * 4 + 1]),
                                              to_tf32(o[f * 4 + 2]), to_tf32(o[f * 4 + 3]));
    }
}

// ---------------- launcher ----------------
extern "C" void kernel_launch(void* const* d_in, const int* in_sizes, int n_in,
                              void* d_out, int out_size) {
    int base = (n_in >= 16) ? 3 : 1;
    const float* x      = (const float*)d_in[0];
    const float* qkv_w  = (const float*)d_in[base + 0];
    const float* qkv_b  = (const float*)d_in[base + 1];
    const float* proj_w = (const float*)d_in[base + 2];
    const float* proj_b = (const float*)d_in[base + 3];
    const float* rpb    = (const float*)d_in[base + 4];
    const float* n1w    = (const float*)d_in[base + 5];
    const float* n1b    = (const float*)d_in[base + 6];
    const float* n2w    = (const float*)d_in[base + 7];
    const float* n2b    = (const float*)d_in[base + 8];
    const float* w1     = (const float*)d_in[base + 9];
    const float* b1     = (const float*)d_in[base + 10];
    const float* w2     = (const float*)d_in[base + 11];
    const float* b2     = (const float*)d_in[base + 12];
    float* out = (float*)d_out;

    cudaFuncSetAttribute(k_mma<0, 192>, cudaFuncAttributeMaxDynamicSharedMemorySize, MMA_SMEM);
    cudaFuncSetAttribute(k_mma<1, 192>, cudaFuncAttributeMaxDynamicSharedMemorySize, MMA_SMEM);
    cudaFuncSetAttribute(k_mma<2, 192>, cudaFuncAttributeMaxDynamicSharedMemorySize, MMA_SMEM);
    cudaFuncSetAttribute(k_mma<3, 768>, cudaFuncAttributeMaxDynamicSharedMemorySize, MMA_SMEM);

    float* g_wt_p;
    cudaGetSymbolAddress((void**)&g_wt_p, g_wt);

    const int nblk_ln = MTOK / 8;
    const int mt = MTOK / 128;         // 3136

    // weight transposes (tf32-rounded)
    k_tr<<<(192 * 576 + 255) / 256, 256>>>(qkv_w, g_wt_p + WT_QKV, 192, 576);
    k_tr<<<(192 * 192 + 255) / 256, 256>>>(proj_w, g_wt_p + WT_PRJ, 192, 192);
    k_tr<<<(192 * 768 + 255) / 256, 256>>>(w1, g_wt_p + WT_M1, 192, 768);
    k_tr<<<(768 * 192 + 255) / 256, 256>>>(w2, g_wt_p + WT_M2, 768, 192);

    // 1. LN1 + shifted-window gather -> g_h
    k_ln<0><<<nblk_ln, 256>>>(x, n1w, n1b);
    // 2. QKV GEMM -> g_qkv
    k_mma<0, 192><<<dim3(6, mt), 256, MMA_SMEM>>>(g_wt_p + WT_QKV, qkv_b, nullptr, nullptr);
    // 3. window attention -> g_att
    k_attn<<<dim3(NWTOT, NH), 64>>>(rpb);
    // 4. proj GEMM + reverse roll + residual -> g_y
    k_mma<1, 192><<<dim3(2, mt), 256, MMA_SMEM>>>(g_wt_p + WT_PRJ, proj_b, x, nullptr);
    // 5. LN2 -> g_att
    k_ln<1><<<nblk_ln, 256>>>(x, n2w, n2b);
    // 6. MLP1 + gelu -> g_h
    k_mma<2, 192><<<dim3(8, mt), 256, MMA_SMEM>>>(g_wt_p + WT_M1, b1, nullptr, nullptr);
    // 7. MLP2 + residual -> d_out
    k_mma<3, 768><<<dim3(2, mt), 256, MMA_SMEM>>>(g_wt_p + WT_M2, b2, nullptr, out);
}

// round 5
// speedup vs baseline: 3.2629x; 1.9231x over previous
#include <cuda_runtime.h>
#include <cuda_bf16.h>
#include <stdint.h>
#include <math.h>

using u32 = unsigned int;
using bf16 = __nv_bfloat16;
using bf162 = __nv_bfloat162;

// ---------------- problem constants ----------------
constexpr int BATCH = 8;
constexpr int HWP   = 224;
constexpr int LPIX  = HWP * HWP;      // 50176
constexpr int DIM   = 192;
constexpr int NH    = 6;
constexpr int HD    = 32;
constexpr int DFF   = 768;
constexpr int WSZ   = 7;
constexpr int SHF   = 3;
constexpr int NTOK  = 49;
constexpr int NWTOT = 8192;
constexpr int MTOK  = BATCH * LPIX;   // 401408

// ---------------- scratch globals ----------------
__device__ bf16  g_qkv[(size_t)MTOK * 3 * DIM];
__device__ bf16  g_att[(size_t)MTOK * DIM];
__device__ float g_y  [(size_t)MTOK * DIM];       // residual stream (fp32!)
__device__ bf16  g_h  [(size_t)MTOK * DFF];
__device__ bf16  g_wt [442368];                   // transposed bf16 weights

constexpr int WT_QKV = 0;        // [576][192]
constexpr int WT_PRJ = 110592;   // [192][192]
constexpr int WT_M1  = 147456;   // [768][192]
constexpr int WT_M2  = 294912;   // [192][768]

// ---------------- helpers ----------------
__device__ __forceinline__ void mma16(float* c, const u32* a, const u32* b) {
    asm volatile(
        "mma.sync.aligned.m16n8k16.row.col.f32.bf16.bf16.f32 "
        "{%0,%1,%2,%3}, {%4,%5,%6,%7}, {%8,%9}, {%0,%1,%2,%3};"
        : "+f"(c[0]), "+f"(c[1]), "+f"(c[2]), "+f"(c[3])
        : "r"(a[0]), "r"(a[1]), "r"(a[2]), "r"(a[3]), "r"(b[0]), "r"(b[1]));
}
// reverse window-partition + roll(+3): window-order token m -> pixel row base
__device__ __forceinline__ size_t scat_row(int m) {
    int bw = m / NTOK, n = m - bw * NTOK;
    int bb = bw >> 10, wdx = bw & 1023;
    int wi = wdx >> 5, wj = wdx & 31;
    int r = n / WSZ, cc = n - r * WSZ;
    int pi = wi * WSZ + r + SHF; if (pi >= HWP) pi -= HWP;
    int pj = wj * WSZ + cc + SHF; if (pj >= HWP) pj -= HWP;
    return ((size_t)bb * LPIX + (size_t)pi * HWP + pj) * DIM;
}

// ---------------- weight transpose fp32 -> bf16 ----------------
__global__ void k_tr(const float* __restrict__ W, bf16* __restrict__ WT, int K, int N) {
    int i = blockIdx.x * 256 + threadIdx.x;
    if (i < K * N) {
        int k = i / N, n = i - k * N;
        WT[(size_t)n * K + k] = __float2bfloat16(W[i]);
    }
}

// ---------------- LayerNorm (one warp / token), bf16 outputs ----------
template <int PHASE>
__global__ void __launch_bounds__(256) k_ln(const float* __restrict__ xin,
                                            const float* __restrict__ w,
                                            const float* __restrict__ b) {
    int warp = threadIdx.x >> 5, lane = threadIdx.x & 31;
    int m = blockIdx.x * 8 + warp;
    const float* src;
    bf16* dst;
    if (PHASE == 0) {
        int bw = m / NTOK, n = m - bw * NTOK;
        int bb = bw >> 10, wdx = bw & 1023;
        int wi = wdx >> 5, wj = wdx & 31;
        int r = n / WSZ, c = n - r * WSZ;
        int pi = wi * WSZ + r + SHF; if (pi >= HWP) pi -= HWP;
        int pj = wj * WSZ + c + SHF; if (pj >= HWP) pj -= HWP;
        src = xin + ((size_t)bb * LPIX + (size_t)pi * HWP + pj) * DIM;
        dst = g_h + (size_t)m * DIM;
    } else {
        src = g_y + (size_t)m * DIM;
        dst = g_att + (size_t)m * DIM;
    }
    float v[6]; float s = 0.f, s2 = 0.f;
#pragma unroll
    for (int j = 0; j < 6; j++) {
        v[j] = src[lane + 32 * j];
        s += v[j]; s2 += v[j] * v[j];
    }
#pragma unroll
    for (int o = 16; o > 0; o >>= 1) {
        s  += __shfl_xor_sync(0xffffffffu, s,  o);
        s2 += __shfl_xor_sync(0xffffffffu, s2, o);
    }
    float mu  = s * (1.f / DIM);
    float var = s2 * (1.f / DIM) - mu * mu;
    float rs  = rsqrtf(var + 1e-5f);
#pragma unroll
    for (int j = 0; j < 6; j++) {
        int kk = lane + 32 * j;
        dst[kk] = __float2bfloat16((v[j] - mu) * rs * __ldg(&w[kk]) + __ldg(&b[kk]));
    }
}

// ---------------- bf16 mma.sync GEMM: C[M,N] = A[M,K] @ W[K,N] -----------
// BM=128, BN=96, K staged 192/chunk in smem (pitch 200 bf16 -> conflict-free).
// 8 warps 2x4, warp tile 64x24 (4 m x 3 n of m16n8k16). 89.6KB smem -> 2 CTA/SM.
// MODE 0: A=g_h    -> g_qkv (bf16, +qkv_b)
// MODE 1: A=g_att  -> scatter + residual into g_y (fp32, +proj_b)
// MODE 2: A=g_att  -> gelu -> g_h (bf16, +b1)
// MODE 3: A=g_h    -> d_out = g_y + acc (fp32, +b2)
constexpr int PITCH2 = 200;
constexpr int MMA_SMEM = (128 + 96) * PITCH2 * 2;   // 89,600 B

template <int MODE, int KTOT>
__global__ void __launch_bounds__(256, 2) k_mma(const bf16* __restrict__ WT,
                                                const float* __restrict__ bias,
                                                const float* __restrict__ aux,
                                                float* __restrict__ dout) {
    extern __shared__ bf16 smb[];
    bf16* As = smb;                      // [128][200]
    bf16* Bs = smb + 128 * PITCH2;       // [96][200]

    const int t = threadIdx.x;
    const int n0 = blockIdx.x * 96;
    const int m0 = blockIdx.y * 128;
    const bf16* A = (MODE == 0 || MODE == 3) ? g_h : g_att;

    const int lane = t & 31, w = t >> 5;
    const int mw = (w >> 2) * 64;        // 0 or 64
    const int nw = (w & 3) * 24;         // 0,24,48,72
    const int g = lane >> 2, tg = lane & 3;

    float acc[4][3][4];
#pragma unroll
    for (int i = 0; i < 4; i++)
#pragma unroll
        for (int j = 0; j < 3; j++)
#pragma unroll
            for (int q = 0; q < 4; q++) acc[i][j][q] = 0.f;

    constexpr int NC = KTOT / 192;
#pragma unroll 1
    for (int c = 0; c < NC; c++) {
        if (c) __syncthreads();
        // stage A: 128 rows x 24 float4 (8 bf16 each)
#pragma unroll
        for (int it = 0; it < 12; it++) {
            int id = t + it * 256;
            int row = id / 24, f = id - row * 24;
            float4 v = *(const float4*)(A + (size_t)(m0 + row) * KTOT + c * 192 + f * 8);
            *(float4*)(As + row * PITCH2 + f * 8) = v;
        }
        // stage B: 96 rows x 24 float4
#pragma unroll
        for (int it = 0; it < 9; it++) {
            int id = t + it * 256;
            int row = id / 24, f = id - row * 24;
            float4 v = *(const float4*)(WT + (size_t)(n0 + row) * KTOT + c * 192 + f * 8);
            *(float4*)(Bs + row * PITCH2 + f * 8) = v;
        }
        __syncthreads();

#pragma unroll 4
        for (int ks = 0; ks < 12; ks++) {
            int k0 = ks * 16;
            u32 a[4][4], b[3][2];
#pragma unroll
            for (int i = 0; i < 4; i++) {
                const bf16* p = As + (mw + i * 16 + g) * PITCH2 + k0 + 2 * tg;
                a[i][0] = *(const u32*)(p);
                a[i][1] = *(const u32*)(p + 8 * PITCH2);
                a[i][2] = *(const u32*)(p + 8);
                a[i][3] = *(const u32*)(p + 8 * PITCH2 + 8);
            }
#pragma unroll
            for (int j = 0; j < 3; j++) {
                const bf16* p = Bs + (nw + j * 8 + g) * PITCH2 + k0 + 2 * tg;
                b[j][0] = *(const u32*)(p);
                b[j][1] = *(const u32*)(p + 8);
            }
#pragma unroll
            for (int i = 0; i < 4; i++)
#pragma unroll
                for (int j = 0; j < 3; j++) mma16(acc[i][j], a[i], b[j]);
        }
    }

    // ---------------- epilogue (register -> global, per MODE) ------------
#pragma unroll
    for (int i = 0; i < 4; i++) {
        int r0 = m0 + mw + i * 16 + g;      // rows r0 and r0+8
#pragma unroll
        for (int half = 0; half < 2; half++) {
            int m = r0 + half * 8;
            size_t srow;
            if (MODE == 1) srow = scat_row(m);
#pragma unroll
            for (int j = 0; j < 3; j++) {
                int col = n0 + nw + j * 8 + 2 * tg;
                float v0 = acc[i][j][half * 2 + 0] + __ldg(&bias[col]);
                float v1 = acc[i][j][half * 2 + 1] + __ldg(&bias[col + 1]);
                if (MODE == 0) {
                    *(bf162*)(g_qkv + (size_t)m * 576 + col) =
                        __float22bfloat162_rn(make_float2(v0, v1));
                } else if (MODE == 1) {
                    float2 xr = *(const float2*)(aux + srow + col);
                    *(float2*)(g_y + srow + col) = make_float2(xr.x + v0, xr.y + v1);
                } else if (MODE == 2) {
                    v0 = 0.5f * v0 * (1.f + erff(v0 * 0.70710678118654752f));
                    v1 = 0.5f * v1 * (1.f + erff(v1 * 0.70710678118654752f));
                    *(bf162*)(g_h + (size_t)m * DFF + col) =
                        __float22bfloat162_rn(make_float2(v0, v1));
                } else {
                    const float* yy = g_y + (size_t)m * DIM + col;
                    *(float2*)(dout + (size_t)m * DIM + col) =
                        make_float2(yy[0] + v0, yy[1] + v1);
                }
            }
        }
    }
}

// ---------------- windowed attention: thread-per-query, broadcast K/V -----
__global__ void __launch_bounds__(64) k_attn(const float* __restrict__ rpb) {
    __shared__ float qs[NTOK][33];
    __shared__ __align__(16) float ks[NTOK][32];
    __shared__ __align__(16) float vs[NTOK][32];
    __shared__ float bs[169];

    const int bw = blockIdx.x, h = blockIdx.y, t = threadIdx.x;
    const int wdx = bw & 1023, wi = wdx >> 5, wj = wdx & 31;
    const bf16* base = g_qkv + (size_t)bw * NTOK * 576 + h * HD;

    for (int e = t; e < NTOK * 16; e += 64) {
        int n = e >> 4, f = e & 15;
        const bf16* row = base + (size_t)n * 576;
        float2 qv = __bfloat1622float2(*(const bf162*)(row + 2 * f));
        qs[n][2 * f] = qv.x; qs[n][2 * f + 1] = qv.y;
        float2 kv = __bfloat1622float2(*(const bf162*)(row + DIM + 2 * f));
        ks[n][2 * f] = kv.x; ks[n][2 * f + 1] = kv.y;
        float2 vv = __bfloat1622float2(*(const bf162*)(row + 2 * DIM + 2 * f));
        vs[n][2 * f] = vv.x; vs[n][2 * f + 1] = vv.y;
    }
    for (int e = t; e < 169; e += 64) bs[e] = rpb[e * NH + h];
    __syncthreads();

    if (t >= NTOK) return;

    const int r1 = t / WSZ, c1 = t - r1 * WSZ;
    const int i1 = wi * WSZ + r1, j1 = wj * WSZ + c1;
    const int h1 = (i1 < HWP - WSZ) ? 0 : ((i1 < HWP - SHF) ? 1 : 2);
    const int g1 = (j1 < HWP - WSZ) ? 0 : ((j1 < HWP - SHF) ? 1 : 2);
    const float scale = 0.17677669529663687f;

    float q[HD];
#pragma unroll
    for (int d = 0; d < HD; d++) q[d] = qs[t][d];

    float p[NTOK];
#pragma unroll
    for (int mk = 0; mk < NTOK; mk++) {
        float s = 0.f;
#pragma unroll
        for (int f = 0; f < 8; f++) {
            float4 kv = *(const float4*)(&ks[mk][f * 4]);     // broadcast
            s += q[f * 4 + 0] * kv.x + q[f * 4 + 1] * kv.y
               + q[f * 4 + 2] * kv.z + q[f * 4 + 3] * kv.w;
        }
        int r2 = mk / WSZ, c2 = mk - r2 * WSZ;
        s = s * scale + bs[(r1 - r2 + 6) * 13 + (c1 - c2 + 6)];
        int i2 = wi * WSZ + r2, j2 = wj * WSZ + c2;
        int h2 = (i2 < HWP - WSZ) ? 0 : ((i2 < HWP - SHF) ? 1 : 2);
        int g2 = (j2 < HWP - WSZ) ? 0 : ((j2 < HWP - SHF) ? 1 : 2);
        if (h1 != h2 || g1 != g2) s -= 100.f;
        p[mk] = s;
    }

    float mx = -1e30f;
#pragma unroll
    for (int j = 0; j < NTOK; j++) mx = fmaxf(mx, p[j]);
    float sum = 0.f;
#pragma unroll
    for (int j = 0; j < NTOK; j++) { p[j] = __expf(p[j] - mx); sum += p[j]; }
    float inv = 1.f / sum;
#pragma unroll
    for (int j = 0; j < NTOK; j++) p[j] *= inv;

    float o[HD];
#pragma unroll
    for (int d = 0; d < HD; d++) o[d] = 0.f;
#pragma unroll
    for (int mk = 0; mk < NTOK; mk++) {
        float pm = p[mk];
#pragma unroll
        for (int f = 0; f < 8; f++) {
            float4 vv = *(const float4*)(&vs[mk][f * 4]);     // broadcast
            o[f * 4 + 0] += pm * vv.x; o[f * 4 + 1] += pm * vv.y;
            o[f * 4 + 2] += pm * vv.z; o[f * 4 + 3] += pm * vv.w;
        }
    }
    bf162* dst = (bf162*)(g_att + ((size_t)(bw * NTOK + t)) * DIM + h * HD);
#pragma unroll
    for (int f = 0; f < 16; f++)
        dst[f] = __float22bfloat162_rn(make_float2(o[2 * f], o[2 * f + 1]));
}

// ---------------- launcher ----------------
extern "C" void kernel_launch(void* const* d_in, const int* in_sizes, int n_in,
                              void* d_out, int out_size) {
    int base = (n_in >= 16) ? 3 : 1;
    const float* x      = (const float*)d_in[0];
    const float* qkv_w  = (const float*)d_in[base + 0];
    const float* qkv_b  = (const float*)d_in[base + 1];
    const float* proj_w = (const float*)d_in[base + 2];
    const float* proj_b = (const float*)d_in[base + 3];
    const float* rpb    = (const float*)d_in[base + 4];
    const float* n1w    = (const float*)d_in[base + 5];
    const float* n1b    = (const float*)d_in[base + 6];
    const float* n2w    = (const float*)d_in[base + 7];
    const float* n2b    = (const float*)d_in[base + 8];
    const float* w1     = (const float*)d_in[base + 9];
    const float* b1     = (const float*)d_in[base + 10];
    const float* w2     = (const float*)d_in[base + 11];
    const float* b2     = (const float*)d_in[base + 12];
    float* out = (float*)d_out;

    cudaFuncSetAttribute(k_mma<0, 192>, cudaFuncAttributeMaxDynamicSharedMemorySize, MMA_SMEM);
    cudaFuncSetAttribute(k_mma<1, 192>, cudaFuncAttributeMaxDynamicSharedMemorySize, MMA_SMEM);
    cudaFuncSetAttribute(k_mma<2, 192>, cudaFuncAttributeMaxDynamicSharedMemorySize, MMA_SMEM);
    cudaFuncSetAttribute(k_mma<3, 768>, cudaFuncAttributeMaxDynamicSharedMemorySize, MMA_SMEM);

    bf16* g_wt_p;
    cudaGetSymbolAddress((void**)&g_wt_p, g_wt);

    const int nblk_ln = MTOK / 8;
    const int mt = MTOK / 128;         // 3136

    // weight transposes (fp32 -> bf16)
    k_tr<<<(192 * 576 + 255) / 256, 256>>>(qkv_w, g_wt_p + WT_QKV, 192, 576);
    k_tr<<<(192 * 192 + 255) / 256, 256>>>(proj_w, g_wt_p + WT_PRJ, 192, 192);
    k_tr<<<(192 * 768 + 255) / 256, 256>>>(w1, g_wt_p + WT_M1, 192, 768);
    k_tr<<<(768 * 192 + 255) / 256, 256>>>(w2, g_wt_p + WT_M2, 768, 192);

    // 1. LN1 + shifted-window gather -> g_h (bf16)
    k_ln<0><<<nblk_ln, 256>>>(x, n1w, n1b);
    // 2. QKV GEMM -> g_qkv (bf16)
    k_mma<0, 192><<<dim3(6, mt), 256, MMA_SMEM>>>(g_wt_p + WT_QKV, qkv_b, nullptr, nullptr);
    // 3. window attention -> g_att (bf16)
    k_attn<<<dim3(NWTOT, NH), 64>>>(rpb);
    // 4. proj GEMM + reverse roll + residual -> g_y (fp32)
    k_mma<1, 192><<<dim3(2, mt), 256, MMA_SMEM>>>(g_wt_p + WT_PRJ, proj_b, x, nullptr);
    // 5. LN2 -> g_att (bf16)
    k_ln<1><<<nblk_ln, 256>>>(x, n2w, n2b);
    // 6. MLP1 + gelu -> g_h (bf16)
    k_mma<2, 192><<<dim3(8, mt), 256, MMA_SMEM>>>(g_wt_p + WT_M1, b1, nullptr, nullptr);
    // 7. MLP2 + residual -> d_out (fp32)
    k_mma<3, 768><<<dim3(2, mt), 256, MMA_SMEM>>>(g_wt_p + WT_M2, b2, nullptr, out);
}

// round 6
// speedup vs baseline: 3.5377x; 1.0842x over previous
#include <cuda_runtime.h>
#include <cuda_bf16.h>
#include <stdint.h>
#include <math.h>

using u32 = unsigned int;
using bf16 = __nv_bfloat16;
using bf162 = __nv_bfloat162;

// ---------------- problem constants ----------------
constexpr int BATCH = 8;
constexpr int HWP   = 224;
constexpr int LPIX  = HWP * HWP;      // 50176
constexpr int DIM   = 192;
constexpr int NH    = 6;
constexpr int HD    = 32;
constexpr int DFF   = 768;
constexpr int WSZ   = 7;
constexpr int SHF   = 3;
constexpr int NTOK  = 49;
constexpr int NWTOT = 8192;
constexpr int MTOK  = BATCH * LPIX;   // 401408

// ---------------- scratch globals ----------------
__device__ bf16  g_qkv[(size_t)MTOK * 3 * DIM];
__device__ bf16  g_att[(size_t)MTOK * DIM];
__device__ float g_y  [(size_t)MTOK * DIM];       // residual stream (fp32)
__device__ bf16  g_h  [(size_t)MTOK * DFF];
__device__ bf16  g_wt [442368];                   // transposed bf16 weights

constexpr int WT_QKV = 0;        // [576][192]
constexpr int WT_PRJ = 110592;   // [192][192]
constexpr int WT_M1  = 147456;   // [768][192]
constexpr int WT_M2  = 294912;   // [192][768]

// ---------------- PTX helpers ----------------
__device__ __forceinline__ void mma16(float* c, const u32* a, const u32* b) {
    asm volatile(
        "mma.sync.aligned.m16n8k16.row.col.f32.bf16.bf16.f32 "
        "{%0,%1,%2,%3}, {%4,%5,%6,%7}, {%8,%9}, {%0,%1,%2,%3};"
        : "+f"(c[0]), "+f"(c[1]), "+f"(c[2]), "+f"(c[3])
        : "r"(a[0]), "r"(a[1]), "r"(a[2]), "r"(a[3]), "r"(b[0]), "r"(b[1]));
}
__device__ __forceinline__ void ldsm_x4(u32* r, u32 addr) {
    asm volatile("ldmatrix.sync.aligned.m8n8.x4.shared.b16 {%0,%1,%2,%3}, [%4];"
        : "=r"(r[0]), "=r"(r[1]), "=r"(r[2]), "=r"(r[3]) : "r"(addr));
}
__device__ __forceinline__ void ldsm_x2(u32* r, u32 addr) {
    asm volatile("ldmatrix.sync.aligned.m8n8.x2.shared.b16 {%0,%1}, [%2];"
        : "=r"(r[0]), "=r"(r[1]) : "r"(addr));
}
__device__ __forceinline__ u32 smem_u32(const void* p) {
    u32 a; asm("{ .reg .u64 t; cvta.to.shared.u64 t, %1; cvt.u32.u64 %0, t; }" : "=r"(a) : "l"(p));
    return a;
}
__device__ __forceinline__ void cpa16(u32 saddr, const void* gaddr) {
    asm volatile("cp.async.cg.shared.global [%0], [%1], 16;" :: "r"(saddr), "l"(gaddr));
}
#define CP_COMMIT() asm volatile("cp.async.commit_group;" ::: "memory")
#define CP_WAIT1()  asm volatile("cp.async.wait_group 1;" ::: "memory")
#define CP_WAIT0()  asm volatile("cp.async.wait_group 0;" ::: "memory")

// reverse window-partition + roll(+3): window-order token m -> pixel row base
__device__ __forceinline__ size_t scat_row(int m) {
    int bw = m / NTOK, n = m - bw * NTOK;
    int bb = bw >> 10, wdx = bw & 1023;
    int wi = wdx >> 5, wj = wdx & 31;
    int r = n / WSZ, cc = n - r * WSZ;
    int pi = wi * WSZ + r + SHF; if (pi >= HWP) pi -= HWP;
    int pj = wj * WSZ + cc + SHF; if (pj >= HWP) pj -= HWP;
    return ((size_t)bb * LPIX + (size_t)pi * HWP + pj) * DIM;
}

// ---------------- weight transpose fp32 -> bf16 ----------------
__global__ void k_tr(const float* __restrict__ W, bf16* __restrict__ WT, int K, int N) {
    int i = blockIdx.x * 256 + threadIdx.x;
    if (i < K * N) {
        int k = i / N, n = i - k * N;
        WT[(size_t)n * K + k] = __float2bfloat16(W[i]);
    }
}

// ---------------- LayerNorm (one warp / token), bf16 outputs ----------
template <int PHASE>
__global__ void __launch_bounds__(256) k_ln(const float* __restrict__ xin,
                                            const float* __restrict__ w,
                                            const float* __restrict__ b) {
    int warp = threadIdx.x >> 5, lane = threadIdx.x & 31;
    int m = blockIdx.x * 8 + warp;
    const float* src;
    bf16* dst;
    if (PHASE == 0) {
        int bw = m / NTOK, n = m - bw * NTOK;
        int bb = bw >> 10, wdx = bw & 1023;
        int wi = wdx >> 5, wj = wdx & 31;
        int r = n / WSZ, c = n - r * WSZ;
        int pi = wi * WSZ + r + SHF; if (pi >= HWP) pi -= HWP;
        int pj = wj * WSZ + c + SHF; if (pj >= HWP) pj -= HWP;
        src = xin + ((size_t)bb * LPIX + (size_t)pi * HWP + pj) * DIM;
        dst = g_h + (size_t)m * DIM;
    } else {
        src = g_y + (size_t)m * DIM;
        dst = g_att + (size_t)m * DIM;
    }
    float v[6]; float s = 0.f, s2 = 0.f;
#pragma unroll
    for (int j = 0; j < 6; j++) {
        v[j] = src[lane + 32 * j];
        s += v[j]; s2 += v[j] * v[j];
    }
#pragma unroll
    for (int o = 16; o > 0; o >>= 1) {
        s  += __shfl_xor_sync(0xffffffffu, s,  o);
        s2 += __shfl_xor_sync(0xffffffffu, s2, o);
    }
    float mu  = s * (1.f / DIM);
    float var = s2 * (1.f / DIM) - mu * mu;
    float rs  = rsqrtf(var + 1e-5f);
#pragma unroll
    for (int j = 0; j < 6; j++) {
        int kk = lane + 32 * j;
        dst[kk] = __float2bfloat16((v[j] - mu) * rs * __ldg(&w[kk]) + __ldg(&b[kk]));
    }
}

// ---------------- bf16 mma.sync GEMM with ldmatrix + cp.async ------------
// BM=128, BN=96. K consumed in 96-wide sub-chunks through a 2-deep cp.async
// pipeline over the two halves of a 192-wide smem buffer (pitch 200).
// 8 warps 2x4, warp tile 64x24. 89.6KB smem -> 2 CTA/SM.
// MODE 0: A=g_h    -> g_qkv (bf16, +qkv_b)
// MODE 1: A=g_att  -> scatter + residual into g_y (fp32, +proj_b)
// MODE 2: A=g_att  -> gelu -> g_h (bf16, +b1)
// MODE 3: A=g_h    -> d_out = g_y + acc (fp32, +b2)
constexpr int PITCH2 = 200;
constexpr int MMA_SMEM = (128 + 96) * PITCH2 * 2;   // 89,600 B

template <int MODE, int KTOT>
__global__ void __launch_bounds__(256, 2) k_mma(const bf16* __restrict__ WT,
                                                const float* __restrict__ bias,
                                                const float* __restrict__ aux,
                                                float* __restrict__ dout) {
    extern __shared__ bf16 smb[];
    bf16* As = smb;                      // [128][200]
    bf16* Bs = smb + 128 * PITCH2;       // [96][200]

    const int t = threadIdx.x;
    const int n0 = blockIdx.x * 96;
    const int m0 = blockIdx.y * 128;
    const bf16* A = (MODE == 0 || MODE == 3) ? g_h : g_att;

    const int lane = t & 31, w = t >> 5;
    const int mw = (w >> 2) * 64;        // 0 or 64
    const int nw = (w & 3) * 24;         // 0,24,48,72
    const int g = lane >> 2, tg = lane & 3;

    const u32 uA = smem_u32(As), uB = smem_u32(Bs);
    // ldmatrix per-lane base addresses
    const u32 aq  = uA + (u32)(((mw + (lane & 15)) * PITCH2 + (lane >> 4) * 8) * 2);
    const int rb  = ((lane >> 4) << 3) + (lane & 7);
    const int kbo = ((lane >> 3) & 1) * 8;
    const u32 bq4 = uB + (u32)(((nw + rb) * PITCH2 + kbo) * 2);
    const u32 bq2 = uB + (u32)(((nw + 16 + rb) * PITCH2 + kbo) * 2);

    float acc[4][3][4] = {};

    constexpr int NSUB = KTOT / 96;

    auto stage = [&](int s) {
        const int hf = (s & 1) * 96;
        // A: 128 rows x 12 float4
        for (int id = t; id < 1536; id += 256) {
            int row = id / 12, f = id - row * 12;
            cpa16(uA + (u32)((row * PITCH2 + hf + f * 8) * 2),
                  A + (size_t)(m0 + row) * KTOT + s * 96 + f * 8);
        }
        // B: 96 rows x 12 float4
        for (int id = t; id < 1152; id += 256) {
            int row = id / 12, f = id - row * 12;
            cpa16(uB + (u32)((row * PITCH2 + hf + f * 8) * 2),
                  WT + (size_t)(n0 + row) * KTOT + s * 96 + f * 8);
        }
        CP_COMMIT();
    };

    stage(0);
    if (NSUB > 1) stage(1);

#pragma unroll 1
    for (int s = 0; s < NSUB; s++) {
        if (s < NSUB - 1) { CP_WAIT1(); } else { CP_WAIT0(); }
        __syncthreads();
        const int koff = (s & 1) * 96;
#pragma unroll
        for (int ks = 0; ks < 6; ks++) {
            const u32 kb2 = (u32)((koff + ks * 16) * 2);
            u32 a[4][4], b[6];
#pragma unroll
            for (int i = 0; i < 4; i++)
                ldsm_x4(a[i], aq + (u32)(i * 16 * PITCH2 * 2) + kb2);
            ldsm_x4(b, bq4 + kb2);
            ldsm_x2(b + 4, bq2 + kb2);
#pragma unroll
            for (int i = 0; i < 4; i++) {
                mma16(acc[i][0], a[i], b);
                mma16(acc[i][1], a[i], b + 2);
                mma16(acc[i][2], a[i], b + 4);
            }
        }
        __syncthreads();
        if (s + 2 < NSUB) stage(s + 2);
    }

    // ---------------- epilogue (register -> global, per MODE) ------------
#pragma unroll
    for (int i = 0; i < 4; i++) {
        int r0 = m0 + mw + i * 16 + g;      // rows r0 and r0+8
#pragma unroll
        for (int half = 0; half < 2; half++) {
            int m = r0 + half * 8;
            size_t srow;
            if (MODE == 1) srow = scat_row(m);
#pragma unroll
            for (int j = 0; j < 3; j++) {
                int col = n0 + nw + j * 8 + 2 * tg;
                float v0 = acc[i][j][half * 2 + 0] + __ldg(&bias[col]);
                float v1 = acc[i][j][half * 2 + 1] + __ldg(&bias[col + 1]);
                if (MODE == 0) {
                    *(bf162*)(g_qkv + (size_t)m * 576 + col) =
                        __float22bfloat162_rn(make_float2(v0, v1));
                } else if (MODE == 1) {
                    float2 xr = *(const float2*)(aux + srow + col);
                    *(float2*)(g_y + srow + col) = make_float2(xr.x + v0, xr.y + v1);
                } else if (MODE == 2) {
                    v0 = 0.5f * v0 * (1.f + erff(v0 * 0.70710678118654752f));
                    v1 = 0.5f * v1 * (1.f + erff(v1 * 0.70710678118654752f));
                    *(bf162*)(g_h + (size_t)m * DFF + col) =
                        __float22bfloat162_rn(make_float2(v0, v1));
                } else {
                    const float* yy = g_y + (size_t)m * DIM + col;
                    *(float2*)(dout + (size_t)m * DIM + col) =
                        make_float2(yy[0] + v0, yy[1] + v1);
                }
            }
        }
    }
}

// ---------------- windowed attention: thread-per-query, broadcast K/V -----
__global__ void __launch_bounds__(64) k_attn(const float* __restrict__ rpb) {
    __shared__ float qs[NTOK][33];
    __shared__ __align__(16) float ks[NTOK][32];
    __shared__ __align__(16) float vs[NTOK][32];
    __shared__ float bs[169];

    const int bw = blockIdx.x, h = blockIdx.y, t = threadIdx.x;
    const int wdx = bw & 1023, wi = wdx >> 5, wj = wdx & 31;
    const bf16* base = g_qkv + (size_t)bw * NTOK * 576 + h * HD;

    for (int e = t; e < NTOK * 16; e += 64) {
        int n = e >> 4, f = e & 15;
        const bf16* row = base + (size_t)n * 576;
        float2 qv = __bfloat1622float2(*(const bf162*)(row + 2 * f));
        qs[n][2 * f] = qv.x; qs[n][2 * f + 1] = qv.y;
        float2 kv = __bfloat1622float2(*(const bf162*)(row + DIM + 2 * f));
        ks[n][2 * f] = kv.x; ks[n][2 * f + 1] = kv.y;
        float2 vv = __bfloat1622float2(*(const bf162*)(row + 2 * DIM + 2 * f));
        vs[n][2 * f] = vv.x; vs[n][2 * f + 1] = vv.y;
    }
    for (int e = t; e < 169; e += 64) bs[e] = rpb[e * NH + h];
    __syncthreads();

    if (t >= NTOK) return;

    const int r1 = t / WSZ, c1 = t - r1 * WSZ;
    const int i1 = wi * WSZ + r1, j1 = wj * WSZ + c1;
    const int h1 = (i1 < HWP - WSZ) ? 0 : ((i1 < HWP - SHF) ? 1 : 2);
    const int g1 = (j1 < HWP - WSZ) ? 0 : ((j1 < HWP - SHF) ? 1 : 2);
    const float scale = 0.17677669529663687f;

    float q[HD];
#pragma unroll
    for (int d = 0; d < HD; d++) q[d] = qs[t][d];

    float p[NTOK];
#pragma unroll
    for (int mk = 0; mk < NTOK; mk++) {
        float s = 0.f;
#pragma unroll
        for (int f = 0; f < 8; f++) {
            float4 kv = *(const float4*)(&ks[mk][f * 4]);     // broadcast
            s += q[f * 4 + 0] * kv.x + q[f * 4 + 1] * kv.y
               + q[f * 4 + 2] * kv.z + q[f * 4 + 3] * kv.w;
        }
        int r2 = mk / WSZ, c2 = mk - r2 * WSZ;
        s = s * scale + bs[(r1 - r2 + 6) * 13 + (c1 - c2 + 6)];
        int i2 = wi * WSZ + r2, j2 = wj * WSZ + c2;
        int h2 = (i2 < HWP - WSZ) ? 0 : ((i2 < HWP - SHF) ? 1 : 2);
        int g2 = (j2 < HWP - WSZ) ? 0 : ((j2 < HWP - SHF) ? 1 : 2);
        if (h1 != h2 || g1 != g2) s -= 100.f;
        p[mk] = s;
    }

    float mx = -1e30f;
#pragma unroll
    for (int j = 0; j < NTOK; j++) mx = fmaxf(mx, p[j]);
    float sum = 0.f;
#pragma unroll
    for (int j = 0; j < NTOK; j++) { p[j] = __expf(p[j] - mx); sum += p[j]; }
    float inv = 1.f / sum;
#pragma unroll
    for (int j = 0; j < NTOK; j++) p[j] *= inv;

    float o[HD];
#pragma unroll
    for (int d = 0; d < HD; d++) o[d] = 0.f;
#pragma unroll
    for (int mk = 0; mk < NTOK; mk++) {
        float pm = p[mk];
#pragma unroll
        for (int f = 0; f < 8; f++) {
            float4 vv = *(const float4*)(&vs[mk][f * 4]);     // broadcast
            o[f * 4 + 0] += pm * vv.x; o[f * 4 + 1] += pm * vv.y;
            o[f * 4 + 2] += pm * vv.z; o[f * 4 + 3] += pm * vv.w;
        }
    }
    bf162* dst = (bf162*)(g_att + ((size_t)(bw * NTOK + t)) * DIM + h * HD);
#pragma unroll
    for (int f = 0; f < 16; f++)
        dst[f] = __float22bfloat162_rn(make_float2(o[2 * f], o[2 * f + 1]));
}

// ---------------- launcher ----------------
extern "C" void kernel_launch(void* const* d_in, const int* in_sizes, int n_in,
                              void* d_out, int out_size) {
    int base = (n_in >= 16) ? 3 : 1;
    const float* x      = (const float*)d_in[0];
    const float* qkv_w  = (const float*)d_in[base + 0];
    const float* qkv_b  = (const float*)d_in[base + 1];
    const float* proj_w = (const float*)d_in[base + 2];
    const float* proj_b = (const float*)d_in[base + 3];
    const float* rpb    = (const float*)d_in[base + 4];
    const float* n1w    = (const float*)d_in[base + 5];
    const float* n1b    = (const float*)d_in[base + 6];
    const float* n2w    = (const float*)d_in[base + 7];
    const float* n2b    = (const float*)d_in[base + 8];
    const float* w1     = (const float*)d_in[base + 9];
    const float* b1     = (const float*)d_in[base + 10];
    const float* w2     = (const float*)d_in[base + 11];
    const float* b2     = (const float*)d_in[base + 12];
    float* out = (float*)d_out;

    cudaFuncSetAttribute(k_mma<0, 192>, cudaFuncAttributeMaxDynamicSharedMemorySize, MMA_SMEM);
    cudaFuncSetAttribute(k_mma<1, 192>, cudaFuncAttributeMaxDynamicSharedMemorySize, MMA_SMEM);
    cudaFuncSetAttribute(k_mma<2, 192>, cudaFuncAttributeMaxDynamicSharedMemorySize, MMA_SMEM);
    cudaFuncSetAttribute(k_mma<3, 768>, cudaFuncAttributeMaxDynamicSharedMemorySize, MMA_SMEM);

    bf16* g_wt_p;
    cudaGetSymbolAddress((void**)&g_wt_p, g_wt);

    const int nblk_ln = MTOK / 8;
    const int mt = MTOK / 128;         // 3136

    // weight transposes (fp32 -> bf16)
    k_tr<<<(192 * 576 + 255) / 256, 256>>>(qkv_w, g_wt_p + WT_QKV, 192, 576);
    k_tr<<<(192 * 192 + 255) / 256, 256>>>(proj_w, g_wt_p + WT_PRJ, 192, 192);
    k_tr<<<(192 * 768 + 255) / 256, 256>>>(w1, g_wt_p + WT_M1, 192, 768);
    k_tr<<<(768 * 192 + 255) / 256, 256>>>(w2, g_wt_p + WT_M2, 768, 192);

    // 1. LN1 + shifted-window gather -> g_h (bf16)
    k_ln<0><<<nblk_ln, 256>>>(x, n1w, n1b);
    // 2. QKV GEMM -> g_qkv (bf16)
    k_mma<0, 192><<<dim3(6, mt), 256, MMA_SMEM>>>(g_wt_p + WT_QKV, qkv_b, nullptr, nullptr);
    // 3. window attention -> g_att (bf16)
    k_attn<<<dim3(NWTOT, NH), 64>>>(rpb);
    // 4. proj GEMM + reverse roll + residual -> g_y (fp32)
    k_mma<1, 192><<<dim3(2, mt), 256, MMA_SMEM>>>(g_wt_p + WT_PRJ, proj_b, x, nullptr);
    // 5. LN2 -> g_att (bf16)
    k_ln<1><<<nblk_ln, 256>>>(x, n2w, n2b);
    // 6. MLP1 + gelu -> g_h (bf16)
    k_mma<2, 192><<<dim3(8, mt), 256, MMA_SMEM>>>(g_wt_p + WT_M1, b1, nullptr, nullptr);
    // 7. MLP2 + residual -> d_out (fp32)
    k_mma<3, 768><<<dim3(2, mt), 256, MMA_SMEM>>>(g_wt_p + WT_M2, b2, nullptr, out);
}

// round 8
// speedup vs baseline: 3.7113x; 1.0491x over previous
#include <cuda_runtime.h>
#include <cuda_bf16.h>
#include <stdint.h>
#include <math.h>

using u32 = unsigned int;
using u64 = unsigned long long;
using bf16 = __nv_bfloat16;
using bf162 = __nv_bfloat162;

// ---------------- problem constants ----------------
constexpr int BATCH = 8;
constexpr int HWP   = 224;
constexpr int LPIX  = HWP * HWP;      // 50176
constexpr int DIM   = 192;
constexpr int NH    = 6;
constexpr int HD    = 32;
constexpr int DFF   = 768;
constexpr int WSZ   = 7;
constexpr int SHF   = 3;
constexpr int NTOK  = 49;
constexpr int NWTOT = 8192;
constexpr int MTOK  = BATCH * LPIX;   // 401408

// ---------------- scratch globals ----------------
__device__ bf16  g_qkv[(size_t)MTOK * 3 * DIM];
__device__ bf16  g_att[(size_t)MTOK * DIM];
__device__ float g_y  [(size_t)MTOK * DIM];       // residual stream (fp32)
__device__ bf16  g_h  [(size_t)MTOK * DFF];
__device__ bf16  g_wt [442368];                   // transposed bf16 weights

constexpr int WT_QKV = 0;        // [576][192]
constexpr int WT_PRJ = 110592;   // [192][192]
constexpr int WT_M1  = 147456;   // [768][192]
constexpr int WT_M2  = 294912;   // [192][768]

// ---------------- PTX helpers ----------------
__device__ __forceinline__ void mma16(float* c, const u32* a, const u32* b) {
    asm volatile(
        "mma.sync.aligned.m16n8k16.row.col.f32.bf16.bf16.f32 "
        "{%0,%1,%2,%3}, {%4,%5,%6,%7}, {%8,%9}, {%0,%1,%2,%3};"
        : "+f"(c[0]), "+f"(c[1]), "+f"(c[2]), "+f"(c[3])
        : "r"(a[0]), "r"(a[1]), "r"(a[2]), "r"(a[3]), "r"(b[0]), "r"(b[1]));
}
__device__ __forceinline__ void ldsm_x4(u32* r, u32 addr) {
    asm volatile("ldmatrix.sync.aligned.m8n8.x4.shared.b16 {%0,%1,%2,%3}, [%4];"
        : "=r"(r[0]), "=r"(r[1]), "=r"(r[2]), "=r"(r[3]) : "r"(addr));
}
__device__ __forceinline__ void ldsm_x2(u32* r, u32 addr) {
    asm volatile("ldmatrix.sync.aligned.m8n8.x2.shared.b16 {%0,%1}, [%2];"
        : "=r"(r[0]), "=r"(r[1]) : "r"(addr));
}
__device__ __forceinline__ u32 smem_u32(const void* p) {
    u32 a; asm("{ .reg .u64 t; cvta.to.shared.u64 t, %1; cvt.u32.u64 %0, t; }" : "=r"(a) : "l"(p));
    return a;
}
__device__ __forceinline__ void cpa16(u32 saddr, const void* gaddr) {
    asm volatile("cp.async.cg.shared.global [%0], [%1], 16;" :: "r"(saddr), "l"(gaddr));
}
#define CP_COMMIT() asm volatile("cp.async.commit_group;" ::: "memory")
#define CP_WAIT2()  asm volatile("cp.async.wait_group 2;" ::: "memory")
#define CP_WAIT1()  asm volatile("cp.async.wait_group 1;" ::: "memory")
#define CP_WAIT0()  asm volatile("cp.async.wait_group 0;" ::: "memory")

// packed f32x2 (FFMA2)
__device__ __forceinline__ u64 pk2(float x, float y) {
    u64 r; asm("mov.b64 %0, {%1,%2};" : "=l"(r) : "f"(x), "f"(y)); return r;
}
__device__ __forceinline__ void fma2(u64& d, u64 a, u64 b) {
    asm("fma.rn.f32x2 %0, %1, %2, %0;" : "+l"(d) : "l"(a), "l"(b));
}
__device__ __forceinline__ float2 unpk2(u64 v) {
    float lo, hi; asm("mov.b64 {%0,%1}, %2;" : "=f"(lo), "=f"(hi) : "l"(v));
    return make_float2(lo, hi);
}

// reverse window-partition + roll(+3): window-order token m -> pixel row base
__device__ __forceinline__ size_t scat_row(int m) {
    int bw = m / NTOK, n = m - bw * NTOK;
    int bb = bw >> 10, wdx = bw & 1023;
    int wi = wdx >> 5, wj = wdx & 31;
    int r = n / WSZ, cc = n - r * WSZ;
    int pi = wi * WSZ + r + SHF; if (pi >= HWP) pi -= HWP;
    int pj = wj * WSZ + cc + SHF; if (pj >= HWP) pj -= HWP;
    return ((size_t)bb * LPIX + (size_t)pi * HWP + pj) * DIM;
}

// ---------------- weight transpose fp32 -> bf16 ----------------
__global__ void k_tr(const float* __restrict__ W, bf16* __restrict__ WT, int K, int N) {
    int i = blockIdx.x * 256 + threadIdx.x;
    if (i < K * N) {
        int k = i / N, n = i - k * N;
        WT[(size_t)n * K + k] = __float2bfloat16(W[i]);
    }
}

// ---------------- LayerNorm (one warp / token), bf16 outputs ----------
template <int PHASE>
__global__ void __launch_bounds__(256) k_ln(const float* __restrict__ xin,
                                            const float* __restrict__ w,
                                            const float* __restrict__ b) {
    int warp = threadIdx.x >> 5, lane = threadIdx.x & 31;
    int m = blockIdx.x * 8 + warp;
    const float* src;
    bf16* dst;
    if (PHASE == 0) {
        int bw = m / NTOK, n = m - bw * NTOK;
        int bb = bw >> 10, wdx = bw & 1023;
        int wi = wdx >> 5, wj = wdx & 31;
        int r = n / WSZ, c = n - r * WSZ;
        int pi = wi * WSZ + r + SHF; if (pi >= HWP) pi -= HWP;
        int pj = wj * WSZ + c + SHF; if (pj >= HWP) pj -= HWP;
        src = xin + ((size_t)bb * LPIX + (size_t)pi * HWP + pj) * DIM;
        dst = g_h + (size_t)m * DIM;
    } else {
        src = g_y + (size_t)m * DIM;
        dst = g_att + (size_t)m * DIM;
    }
    float v[6]; float s = 0.f, s2 = 0.f;
#pragma unroll
    for (int j = 0; j < 6; j++) {
        v[j] = src[lane + 32 * j];
        s += v[j]; s2 += v[j] * v[j];
    }
#pragma unroll
    for (int o = 16; o > 0; o >>= 1) {
        s  += __shfl_xor_sync(0xffffffffu, s,  o);
        s2 += __shfl_xor_sync(0xffffffffu, s2, o);
    }
    float mu  = s * (1.f / DIM);
    float var = s2 * (1.f / DIM) - mu * mu;
    float rs  = rsqrtf(var + 1e-5f);
#pragma unroll
    for (int j = 0; j < 6; j++) {
        int kk = lane + 32 * j;
        dst[kk] = __float2bfloat16((v[j] - mu) * rs * __ldg(&w[kk]) + __ldg(&b[kk]));
    }
}

// ---------------- bf16 mma.sync GEMM, ldmatrix + ring-3 cp.async ---------
// BM=128, BN=96, K consumed in 64-wide sub-chunks; 3-slot ring inside a
// 192-wide smem buffer (pitch 200), 2 groups always in flight.
// 8 warps 2x4, warp tile 64x24. 89.6KB smem -> 2 CTA/SM.
constexpr int PITCH2 = 200;
constexpr int MMA_SMEM = (128 + 96) * PITCH2 * 2;   // 89,600 B

template <int MODE, int KTOT>
__global__ void __launch_bounds__(256, 2) k_mma(const bf16* __restrict__ WT,
                                                const float* __restrict__ bias,
                                                const float* __restrict__ aux,
                                                float* __restrict__ dout) {
    extern __shared__ bf16 smb[];
    bf16* As = smb;                      // [128][200]
    bf16* Bs = smb + 128 * PITCH2;       // [96][200]

    const int t = threadIdx.x;
    const int n0 = blockIdx.x * 96;
    const int m0 = blockIdx.y * 128;
    const bf16* A = (MODE == 0 || MODE == 3) ? g_h : g_att;

    const int lane = t & 31, w = t >> 5;
    const int mw = (w >> 2) * 64;        // 0 or 64
    const int nw = (w & 3) * 24;         // 0,24,48,72
    const int g = lane >> 2, tg = lane & 3;

    const u32 uA = smem_u32(As), uB = smem_u32(Bs);
    const u32 aq  = uA + (u32)(((mw + (lane & 15)) * PITCH2 + (lane >> 4) * 8) * 2);
    const int rb  = ((lane >> 4) << 3) + (lane & 7);
    const int kbo = ((lane >> 3) & 1) * 8;
    const u32 bq4 = uB + (u32)(((nw + rb) * PITCH2 + kbo) * 2);
    const u32 bq2 = uB + (u32)(((nw + 16 + rb) * PITCH2 + kbo) * 2);

    float acc[4][3][4] = {};

    constexpr int NSUB = KTOT / 64;

    auto stage = [&](int s) {
        const int col = (s % 3) * 64;
#pragma unroll
        for (int it = 0; it < 7; it++) {
            int id = t + it * 256;
            if (id < 1024) {                         // A: 128 rows x 8 float4
                int row = id >> 3, f = id & 7;
                cpa16(uA + (u32)((row * PITCH2 + col + f * 8) * 2),
                      A + (size_t)(m0 + row) * KTOT + s * 64 + f * 8);
            } else {                                 // B: 96 rows x 8 float4
                int id2 = id - 1024;
                int row = id2 >> 3, f = id2 & 7;
                cpa16(uB + (u32)((row * PITCH2 + col + f * 8) * 2),
                      WT + (size_t)(n0 + row) * KTOT + s * 64 + f * 8);
            }
        }
        CP_COMMIT();
    };

    stage(0);
    if (NSUB > 1) stage(1);
    if (NSUB > 2) stage(2);

#pragma unroll 1
    for (int s = 0; s < NSUB; s++) {
        int rem = NSUB - 1 - s;
        if (rem >= 2) { CP_WAIT2(); } else if (rem == 1) { CP_WAIT1(); } else { CP_WAIT0(); }
        __syncthreads();
        const int koff = (s % 3) * 64;
#pragma unroll
        for (int ks = 0; ks < 4; ks++) {
            const u32 kb2 = (u32)((koff + ks * 16) * 2);
            u32 a[4][4], b[6];
#pragma unroll
            for (int i = 0; i < 4; i++)
                ldsm_x4(a[i], aq + (u32)(i * 16 * PITCH2 * 2) + kb2);
            ldsm_x4(b, bq4 + kb2);
            ldsm_x2(b + 4, bq2 + kb2);
#pragma unroll
            for (int i = 0; i < 4; i++) {
                mma16(acc[i][0], a[i], b);
                mma16(acc[i][1], a[i], b + 2);
                mma16(acc[i][2], a[i], b + 4);
            }
        }
        __syncthreads();
        if (s + 3 < NSUB) stage(s + 3);
    }

    // ---------------- epilogue (register -> global, per MODE) ------------
#pragma unroll
    for (int i = 0; i < 4; i++) {
        int r0 = m0 + mw + i * 16 + g;      // rows r0 and r0+8
#pragma unroll
        for (int half = 0; half < 2; half++) {
            int m = r0 + half * 8;
            size_t srow;
            if (MODE == 1) srow = scat_row(m);
#pragma unroll
            for (int j = 0; j < 3; j++) {
                int col = n0 + nw + j * 8 + 2 * tg;
                float v0 = acc[i][j][half * 2 + 0] + __ldg(&bias[col]);
                float v1 = acc[i][j][half * 2 + 1] + __ldg(&bias[col + 1]);
                if (MODE == 0) {
                    *(bf162*)(g_qkv + (size_t)m * 576 + col) =
                        __float22bfloat162_rn(make_float2(v0, v1));
                } else if (MODE == 1) {
                    float2 xr = *(const float2*)(aux + srow + col);
                    *(float2*)(g_y + srow + col) = make_float2(xr.x + v0, xr.y + v1);
                } else if (MODE == 2) {
                    v0 = 0.5f * v0 * (1.f + erff(v0 * 0.70710678118654752f));
                    v1 = 0.5f * v1 * (1.f + erff(v1 * 0.70710678118654752f));
                    *(bf162*)(g_h + (size_t)m * DFF + col) =
                        __float22bfloat162_rn(make_float2(v0, v1));
                } else {
                    const float* yy = g_y + (size_t)m * DIM + col;
                    *(float2*)(dout + (size_t)m * DIM + col) =
                        make_float2(yy[0] + v0, yy[1] + v1);
                }
            }
        }
    }
}

// ---------------- windowed attention: thread-per-query, packed f32x2 -----
__global__ void __launch_bounds__(64) k_attn(const float* __restrict__ rpb) {
    __shared__ float qs[NTOK][33];
    __shared__ __align__(16) ulonglong2 k2[NTOK][8];   // f32x2-packed K rows
    __shared__ __align__(16) ulonglong2 v2[NTOK][8];   // f32x2-packed V rows
    __shared__ float bs[169];
    __shared__ int rid[NTOK];

    const int bw = blockIdx.x, h = blockIdx.y, t = threadIdx.x;
    const int wdx = bw & 1023, wi = wdx >> 5, wj = wdx & 31;
    const bf16* base = g_qkv + (size_t)bw * NTOK * 576 + h * HD;

    // q rows (scalar, padded pitch)
    for (int e = t; e < NTOK * 16; e += 64) {
        int n = e >> 4, f = e & 15;
        float2 qv = __bfloat1622float2(*(const bf162*)(base + (size_t)n * 576 + 2 * f));
        qs[n][2 * f] = qv.x; qs[n][2 * f + 1] = qv.y;
    }
    // K/V rows converted to packed f32x2 quads
    for (int e = t; e < NTOK * 8; e += 64) {
        int n = e >> 3, f = e & 7;
        const bf16* row = base + (size_t)n * 576;
        float2 ka = __bfloat1622float2(*(const bf162*)(row + DIM + 4 * f));
        float2 kb = __bfloat1622float2(*(const bf162*)(row + DIM + 4 * f + 2));
        ulonglong2 kk; kk.x = pk2(ka.x, ka.y); kk.y = pk2(kb.x, kb.y);
        k2[n][f] = kk;
        float2 va = __bfloat1622float2(*(const bf162*)(row + 2 * DIM + 4 * f));
        float2 vb = __bfloat1622float2(*(const bf162*)(row + 2 * DIM + 4 * f + 2));
        ulonglong2 vv; vv.x = pk2(va.x, va.y); vv.y = pk2(vb.x, vb.y);
        v2[n][f] = vv;
    }
    for (int e = t; e < 169; e += 64) bs[e] = rpb[e * NH + h];
    // region ids for shift mask
    for (int e = t; e < NTOK; e += 64) {
        int r2 = e / WSZ, c2 = e - r2 * WSZ;
        int i2 = wi * WSZ + r2, j2 = wj * WSZ + c2;
        int h2 = (i2 < HWP - WSZ) ? 0 : ((i2 < HWP - SHF) ? 1 : 2);
        int g2 = (j2 < HWP - WSZ) ? 0 : ((j2 < HWP - SHF) ? 1 : 2);
        rid[e] = h2 * 3 + g2;
    }
    __syncthreads();

    if (t >= NTOK) return;

    const int r1 = t / WSZ, c1 = t - r1 * WSZ;
    const int myrid = rid[t];
    const float scale = 0.17677669529663687f;

    u64 q2[16];
#pragma unroll
    for (int f = 0; f < 16; f++) q2[f] = pk2(qs[t][2 * f], qs[t][2 * f + 1]);

    float p[NTOK];
#pragma unroll
    for (int mk = 0; mk < NTOK; mk++) {
        u64 acc0 = 0ull, acc1 = 0ull;
#pragma unroll
        for (int f = 0; f < 8; f++) {
            ulonglong2 kk = k2[mk][f];                 // broadcast LDS.128
            fma2(acc0, q2[2 * f], kk.x);
            fma2(acc1, q2[2 * f + 1], kk.y);
        }
        float2 a0 = unpk2(acc0), a1 = unpk2(acc1);
        float s = (a0.x + a0.y) + (a1.x + a1.y);
        int r2 = mk / WSZ, c2 = mk - r2 * WSZ;
        s = s * scale + bs[(r1 - r2 + 6) * 13 + (c1 - c2 + 6)];
        if (myrid != rid[mk]) s -= 100.f;
        p[mk] = s;
    }

    float mx = -1e30f;
#pragma unroll
    for (int j = 0; j < NTOK; j++) mx = fmaxf(mx, p[j]);
    float sum = 0.f;
#pragma unroll
    for (int j = 0; j < NTOK; j++) { p[j] = __expf(p[j] - mx); sum += p[j]; }
    float inv = 1.f / sum;

    u64 o2[16];
#pragma unroll
    for (int f = 0; f < 16; f++) o2[f] = 0ull;
#pragma unroll
    for (int mk = 0; mk < NTOK; mk++) {
        u64 pm = pk2(p[mk], p[mk]);
#pragma unroll
        for (int f = 0; f < 8; f++) {
            ulonglong2 vv = v2[mk][f];                 // broadcast LDS.128
            fma2(o2[2 * f], pm, vv.x);
            fma2(o2[2 * f + 1], pm, vv.y);
        }
    }
    // assemble bf162 words and store as 4x STG.128
    u32 ob[16];
#pragma unroll
    for (int f = 0; f < 16; f++) {
        float2 ov = unpk2(o2[f]);
        bf162 bb = __float22bfloat162_rn(make_float2(ov.x * inv, ov.y * inv));
        ob[f] = *(u32*)&bb;
    }
    bf16* dst = g_att + ((size_t)(bw * NTOK + t)) * DIM + h * HD;
#pragma unroll
    for (int f = 0; f < 4; f++)
        *(uint4*)(dst + f * 8) = make_uint4(ob[4 * f], ob[4 * f + 1],
                                            ob[4 * f + 2], ob[4 * f + 3]);
}

// ---------------- launcher ----------------
extern "C" void kernel_launch(void* const* d_in, const int* in_sizes, int n_in,
                              void* d_out, int out_size) {
    int base = (n_in >= 16) ? 3 : 1;
    const float* x      = (const float*)d_in[0];
    const float* qkv_w  = (const float*)d_in[base + 0];
    const float* qkv_b  = (const float*)d_in[base + 1];
    const float* proj_w = (const float*)d_in[base + 2];
    const float* proj_b = (const float*)d_in[base + 3];
    const float* rpb    = (const float*)d_in[base + 4];
    const float* n1w    = (const float*)d_in[base + 5];
    const float* n1b    = (const float*)d_in[base + 6];
    const float* n2w    = (const float*)d_in[base + 7];
    const float* n2b    = (const float*)d_in[base + 8];
    const float* w1     = (const float*)d_in[base + 9];
    const float* b1     = (const float*)d_in[base + 10];
    const float* w2     = (const float*)d_in[base + 11];
    const float* b2     = (const float*)d_in[base + 12];
    float* out = (float*)d_out;

    cudaFuncSetAttribute(k_mma<0, 192>, cudaFuncAttributeMaxDynamicSharedMemorySize, MMA_SMEM);
    cudaFuncSetAttribute(k_mma<1, 192>, cudaFuncAttributeMaxDynamicSharedMemorySize, MMA_SMEM);
    cudaFuncSetAttribute(k_mma<2, 192>, cudaFuncAttributeMaxDynamicSharedMemorySize, MMA_SMEM);
    cudaFuncSetAttribute(k_mma<3, 768>, cudaFuncAttributeMaxDynamicSharedMemorySize, MMA_SMEM);

    bf16* g_wt_p;
    cudaGetSymbolAddress((void**)&g_wt_p, g_wt);

    const int nblk_ln = MTOK / 8;
    const int mt = MTOK / 128;         // 3136

    // weight transposes (fp32 -> bf16)
    k_tr<<<(192 * 576 + 255) / 256, 256>>>(qkv_w, g_wt_p + WT_QKV, 192, 576);
    k_tr<<<(192 * 192 + 255) / 256, 256>>>(proj_w, g_wt_p + WT_PRJ, 192, 192);
    k_tr<<<(192 * 768 + 255) / 256, 256>>>(w1, g_wt_p + WT_M1, 192, 768);
    k_tr<<<(768 * 192 + 255) / 256, 256>>>(w2, g_wt_p + WT_M2, 768, 192);

    // 1. LN1 + shifted-window gather -> g_h (bf16)
    k_ln<0><<<nblk_ln, 256>>>(x, n1w, n1b);
    // 2. QKV GEMM -> g_qkv (bf16)
    k_mma<0, 192><<<dim3(6, mt), 256, MMA_SMEM>>>(g_wt_p + WT_QKV, qkv_b, nullptr, nullptr);
    // 3. window attention -> g_att (bf16)
    k_attn<<<dim3(NWTOT, NH), 64>>>(rpb);
    // 4. proj GEMM + reverse roll + residual -> g_y (fp32)
    k_mma<1, 192><<<dim3(2, mt), 256, MMA_SMEM>>>(g_wt_p + WT_PRJ, proj_b, x, nullptr);
    // 5. LN2 -> g_att (bf16)
    k_ln<1><<<nblk_ln, 256>>>(x, n2w, n2b);
    // 6. MLP1 + gelu -> g_h (bf16)
    k_mma<2, 192><<<dim3(8, mt), 256, MMA_SMEM>>>(g_wt_p + WT_M1, b1, nullptr, nullptr);
    // 7. MLP2 + residual -> d_out (fp32)
    k_mma<3, 768><<<dim3(2, mt), 256, MMA_SMEM>>>(g_wt_p + WT_M2, b2, nullptr, out);
}

// round 9
// speedup vs baseline: 4.1400x; 1.1155x over previous
#include <cuda_runtime.h>
#include <cuda_bf16.h>
#include <stdint.h>
#include <math.h>

using u32 = unsigned int;
using u64 = unsigned long long;
using bf16 = __nv_bfloat16;
using bf162 = __nv_bfloat162;

// ---------------- problem constants ----------------
constexpr int BATCH = 8;
constexpr int HWP   = 224;
constexpr int LPIX  = HWP * HWP;      // 50176
constexpr int DIM   = 192;
constexpr int NH    = 6;
constexpr int HD    = 32;
constexpr int DFF   = 768;
constexpr int WSZ   = 7;
constexpr int SHF   = 3;
constexpr int NTOK  = 49;
constexpr int NWTOT = 8192;
constexpr int MTOK  = BATCH * LPIX;   // 401408

// ---------------- scratch globals ----------------
__device__ bf16  g_qkv[(size_t)MTOK * 3 * DIM];
__device__ bf16  g_att[(size_t)MTOK * DIM];
__device__ float g_y  [(size_t)MTOK * DIM];       // residual stream (fp32)
__device__ bf16  g_wt [442368];                   // transposed bf16 weights

constexpr int WT_QKV = 0;        // [576][192]
constexpr int WT_PRJ = 110592;   // [192][192]
constexpr int WT_M1  = 147456;   // [768][192]
constexpr int WT_M2  = 294912;   // [192][768]

// g_h only used as LN1 output now (bf16 [MTOK][192])
__device__ bf16  g_h  [(size_t)MTOK * DIM];

// ---------------- PTX helpers ----------------
__device__ __forceinline__ void mma16(float* c, const u32* a, const u32* b) {
    asm volatile(
        "mma.sync.aligned.m16n8k16.row.col.f32.bf16.bf16.f32 "
        "{%0,%1,%2,%3}, {%4,%5,%6,%7}, {%8,%9}, {%0,%1,%2,%3};"
        : "+f"(c[0]), "+f"(c[1]), "+f"(c[2]), "+f"(c[3])
        : "r"(a[0]), "r"(a[1]), "r"(a[2]), "r"(a[3]), "r"(b[0]), "r"(b[1]));
}
__device__ __forceinline__ void ldsm_x4(u32* r, u32 addr) {
    asm volatile("ldmatrix.sync.aligned.m8n8.x4.shared.b16 {%0,%1,%2,%3}, [%4];"
        : "=r"(r[0]), "=r"(r[1]), "=r"(r[2]), "=r"(r[3]) : "r"(addr));
}
__device__ __forceinline__ void ldsm_x2(u32* r, u32 addr) {
    asm volatile("ldmatrix.sync.aligned.m8n8.x2.shared.b16 {%0,%1}, [%2];"
        : "=r"(r[0]), "=r"(r[1]) : "r"(addr));
}
__device__ __forceinline__ u32 smem_u32(const void* p) {
    u32 a; asm("{ .reg .u64 t; cvta.to.shared.u64 t, %1; cvt.u32.u64 %0, t; }" : "=r"(a) : "l"(p));
    return a;
}
__device__ __forceinline__ void cpa16(u32 saddr, const void* gaddr) {
    asm volatile("cp.async.cg.shared.global [%0], [%1], 16;" :: "r"(saddr), "l"(gaddr));
}
#define CP_COMMIT() asm volatile("cp.async.commit_group;" ::: "memory")
#define CP_WAIT2()  asm volatile("cp.async.wait_group 2;" ::: "memory")
#define CP_WAIT1()  asm volatile("cp.async.wait_group 1;" ::: "memory")
#define CP_WAIT0()  asm volatile("cp.async.wait_group 0;" ::: "memory")

// packed f32x2 (FFMA2)
__device__ __forceinline__ u64 pk2(float x, float y) {
    u64 r; asm("mov.b64 %0, {%1,%2};" : "=l"(r) : "f"(x), "f"(y)); return r;
}
__device__ __forceinline__ void fma2(u64& d, u64 a, u64 b) {
    asm("fma.rn.f32x2 %0, %1, %2, %0;" : "+l"(d) : "l"(a), "l"(b));
}
__device__ __forceinline__ float2 unpk2(u64 v) {
    float lo, hi; asm("mov.b64 {%0,%1}, %2;" : "=f"(lo), "=f"(hi) : "l"(v));
    return make_float2(lo, hi);
}

// fast gelu: tanh form (abs err <= ~4e-4, far below bf16 h-rounding)
__device__ __forceinline__ float gelu_f(float v) {
    float u = v * (0.7978845608028654f + 0.035677408136300125f * v * v);
    float th; asm("tanh.approx.f32 %0, %1;" : "=f"(th) : "f"(u));
    return 0.5f * v * (1.f + th);
}

// reverse window-partition + roll(+3): window-order token m -> pixel row base
__device__ __forceinline__ size_t scat_row(int m) {
    int bw = m / NTOK, n = m - bw * NTOK;
    int bb = bw >> 10, wdx = bw & 1023;
    int wi = wdx >> 5, wj = wdx & 31;
    int r = n / WSZ, cc = n - r * WSZ;
    int pi = wi * WSZ + r + SHF; if (pi >= HWP) pi -= HWP;
    int pj = wj * WSZ + cc + SHF; if (pj >= HWP) pj -= HWP;
    return ((size_t)bb * LPIX + (size_t)pi * HWP + pj) * DIM;
}

// ---------------- all weight transposes in one launch --------------------
__global__ void k_trall(const float* __restrict__ qkv_w, const float* __restrict__ proj_w,
                        const float* __restrict__ w1, const float* __restrict__ w2,
                        bf16* __restrict__ wt) {
    int i = blockIdx.x * 256 + threadIdx.x;
    if (i < 110592) {
        int k = i / 576, n = i - k * 576;
        wt[WT_QKV + n * 192 + k] = __float2bfloat16(qkv_w[i]);
    } else if (i < 147456) {
        int j = i - 110592; int k = j / 192, n = j - k * 192;
        wt[WT_PRJ + n * 192 + k] = __float2bfloat16(proj_w[j]);
    } else if (i < 294912) {
        int j = i - 147456; int k = j / 768, n = j - k * 768;
        wt[WT_M1 + n * 192 + k] = __float2bfloat16(w1[j]);
    } else if (i < 442368) {
        int j = i - 294912; int k = j / 192, n = j - k * 192;
        wt[WT_M2 + n * 768 + k] = __float2bfloat16(w2[j]);
    }
}

// ---------------- LayerNorm (one warp / token), bf16 outputs ----------
template <int PHASE>
__global__ void __launch_bounds__(256) k_ln(const float* __restrict__ xin,
                                            const float* __restrict__ w,
                                            const float* __restrict__ b) {
    int warp = threadIdx.x >> 5, lane = threadIdx.x & 31;
    int m = blockIdx.x * 8 + warp;
    const float* src;
    bf16* dst;
    if (PHASE == 0) {
        int bw = m / NTOK, n = m - bw * NTOK;
        int bb = bw >> 10, wdx = bw & 1023;
        int wi = wdx >> 5, wj = wdx & 31;
        int r = n / WSZ, c = n - r * WSZ;
        int pi = wi * WSZ + r + SHF; if (pi >= HWP) pi -= HWP;
        int pj = wj * WSZ + c + SHF; if (pj >= HWP) pj -= HWP;
        src = xin + ((size_t)bb * LPIX + (size_t)pi * HWP + pj) * DIM;
        dst = g_h + (size_t)m * DIM;
    } else {
        src = g_y + (size_t)m * DIM;
        dst = g_att + (size_t)m * DIM;
    }
    float v[6]; float s = 0.f, s2 = 0.f;
#pragma unroll
    for (int j = 0; j < 6; j++) {
        v[j] = src[lane + 32 * j];
        s += v[j]; s2 += v[j] * v[j];
    }
#pragma unroll
    for (int o = 16; o > 0; o >>= 1) {
        s  += __shfl_xor_sync(0xffffffffu, s,  o);
        s2 += __shfl_xor_sync(0xffffffffu, s2, o);
    }
    float mu  = s * (1.f / DIM);
    float var = s2 * (1.f / DIM) - mu * mu;
    float rs  = rsqrtf(var + 1e-5f);
#pragma unroll
    for (int j = 0; j < 6; j++) {
        int kk = lane + 32 * j;
        dst[kk] = __float2bfloat16((v[j] - mu) * rs * __ldg(&w[kk]) + __ldg(&b[kk]));
    }
}

// ---------------- bf16 mma.sync GEMM, ldmatrix + ring-3 cp.async ---------
// (QKV and proj only now.) BM=128, BN=96, 64-wide K sub-chunks.
constexpr int PITCH2 = 200;
constexpr int MMA_SMEM = (128 + 96) * PITCH2 * 2;   // 89,600 B

template <int MODE, int KTOT>
__global__ void __launch_bounds__(256, 2) k_mma(const bf16* __restrict__ WT,
                                                const float* __restrict__ bias,
                                                const float* __restrict__ aux,
                                                float* __restrict__ dout) {
    extern __shared__ bf16 smb[];
    bf16* As = smb;                      // [128][200]
    bf16* Bs = smb + 128 * PITCH2;       // [96][200]

    const int t = threadIdx.x;
    const int n0 = blockIdx.x * 96;
    const int m0 = blockIdx.y * 128;
    const bf16* A = (MODE == 0) ? g_h : g_att;

    const int lane = t & 31, w = t >> 5;
    const int mw = (w >> 2) * 64;
    const int nw = (w & 3) * 24;
    const int g = lane >> 2, tg = lane & 3;

    const u32 uA = smem_u32(As), uB = smem_u32(Bs);
    const u32 aq  = uA + (u32)(((mw + (lane & 15)) * PITCH2 + (lane >> 4) * 8) * 2);
    const int rb  = ((lane >> 4) << 3) + (lane & 7);
    const int kbo = ((lane >> 3) & 1) * 8;
    const u32 bq4 = uB + (u32)(((nw + rb) * PITCH2 + kbo) * 2);
    const u32 bq2 = uB + (u32)(((nw + 16 + rb) * PITCH2 + kbo) * 2);

    float acc[4][3][4] = {};

    constexpr int NSUB = KTOT / 64;

    auto stage = [&](int s) {
        const int col = (s % 3) * 64;
#pragma unroll
        for (int it = 0; it < 7; it++) {
            int id = t + it * 256;
            if (id < 1024) {
                int row = id >> 3, f = id & 7;
                cpa16(uA + (u32)((row * PITCH2 + col + f * 8) * 2),
                      A + (size_t)(m0 + row) * KTOT + s * 64 + f * 8);
            } else {
                int id2 = id - 1024;
                int row = id2 >> 3, f = id2 & 7;
                cpa16(uB + (u32)((row * PITCH2 + col + f * 8) * 2),
                      WT + (size_t)(n0 + row) * KTOT + s * 64 + f * 8);
            }
        }
        CP_COMMIT();
    };

    stage(0);
    if (NSUB > 1) stage(1);
    if (NSUB > 2) stage(2);

#pragma unroll 1
    for (int s = 0; s < NSUB; s++) {
        int rem = NSUB - 1 - s;
        if (rem >= 2) { CP_WAIT2(); } else if (rem == 1) { CP_WAIT1(); } else { CP_WAIT0(); }
        __syncthreads();
        const int koff = (s % 3) * 64;
#pragma unroll
        for (int ks = 0; ks < 4; ks++) {
            const u32 kb2 = (u32)((koff + ks * 16) * 2);
            u32 a[4][4], b[6];
#pragma unroll
            for (int i = 0; i < 4; i++)
                ldsm_x4(a[i], aq + (u32)(i * 16 * PITCH2 * 2) + kb2);
            ldsm_x4(b, bq4 + kb2);
            ldsm_x2(b + 4, bq2 + kb2);
#pragma unroll
            for (int i = 0; i < 4; i++) {
                mma16(acc[i][0], a[i], b);
                mma16(acc[i][1], a[i], b + 2);
                mma16(acc[i][2], a[i], b + 4);
            }
        }
        __syncthreads();
        if (s + 3 < NSUB) stage(s + 3);
    }

#pragma unroll
    for (int i = 0; i < 4; i++) {
        int r0 = m0 + mw + i * 16 + g;
#pragma unroll
        for (int half = 0; half < 2; half++) {
            int m = r0 + half * 8;
            size_t srow;
            if (MODE == 1) srow = scat_row(m);
#pragma unroll
            for (int j = 0; j < 3; j++) {
                int col = n0 + nw + j * 8 + 2 * tg;
                float v0 = acc[i][j][half * 2 + 0] + __ldg(&bias[col]);
                float v1 = acc[i][j][half * 2 + 1] + __ldg(&bias[col + 1]);
                if (MODE == 0) {
                    *(bf162*)(g_qkv + (size_t)m * 576 + col) =
                        __float22bfloat162_rn(make_float2(v0, v1));
                } else {
                    float2 xr = *(const float2*)(aux + srow + col);
                    *(float2*)(g_y + srow + col) = make_float2(xr.x + v0, xr.y + v1);
                }
            }
        }
    }
}

// ---------------- fused MLP: out = gelu(LN2x @ W1 + b1) @ W2 + b2 + g_y ---
// 512 threads, 1 CTA/SM. 8 chunks of 96 hidden dims.
// Phase A: h[128x96] = A[128x192] @ W1chunk (MMA, K=192)
// Phase B: out[128x192] += h @ W2chunk (MMA, K=96), acc in registers.
constexpr int MLP_SMEM = 196096;   // bytes

__global__ void __launch_bounds__(512, 1) k_mlp(const bf16* __restrict__ W1T,
                                                const bf16* __restrict__ W2T,
                                                const float* __restrict__ b1,
                                                const float* __restrict__ b2,
                                                float* __restrict__ dout) {
    extern __shared__ bf16 smb[];
    bf16* Asm = smb;                 // [128][200]  25600 units
    bf16* Hs  = smb + 25600;         // [128][104]  13312
    bf16* W1s = smb + 38912;         // [96][200]   19200
    bf16* W2s = smb + 58112;         // [2][192][104] 39936

    const int t = threadIdx.x;
    const int m0 = blockIdx.x * 128;
    const int lane = t & 31, w = t >> 5;
    const int mwp = (w >> 2) * 32;          // 0,32,64,96
    const int nwA = (w & 3) * 24;           // phase-A n-tile within 96
    const int nwB = (w & 3) * 48;           // phase-B n-tile within 192
    const int g = lane >> 2, tg = lane & 3;

    const u32 uA = smem_u32(Asm), uH = smem_u32(Hs);
    const u32 uW1 = smem_u32(W1s), uW2 = smem_u32(W2s);

    const u32 aqA = uA + (u32)(((mwp + (lane & 15)) * 200 + (lane >> 4) * 8) * 2);
    const u32 aqB = uH + (u32)(((mwp + (lane & 15)) * 104 + (lane >> 4) * 8) * 2);
    const int rb  = ((lane >> 4) << 3) + (lane & 7);
    const int kbo = ((lane >> 3) & 1) * 8;
    const u32 bq4A = uW1 + (u32)(((nwA + rb) * 200 + kbo) * 2);
    const u32 bq2A = uW1 + (u32)(((nwA + 16 + rb) * 200 + kbo) * 2);

    float accB[2][6][4] = {};

    auto stage_A = [&] {
        for (int id = t; id < 3072; id += 512) {
            int row = id / 24, f = id - row * 24;
            cpa16(uA + (u32)((row * 200 + f * 8) * 2),
                  g_att + (size_t)(m0 + row) * DIM + f * 8);
        }
    };
    auto stage_W1 = [&](int c) {
        for (int id = t; id < 2304; id += 512) {
            int row = id / 24, f = id - row * 24;
            cpa16(uW1 + (u32)((row * 200 + f * 8) * 2),
                  W1T + (size_t)(96 * c + row) * DIM + f * 8);
        }
    };
    auto stage_W2 = [&](int c) {
        const u32 base = uW2 + (u32)((c & 1) * 19968 * 2);
        for (int id = t; id < 2304; id += 512) {
            int row = id / 12, f = id - row * 12;
            cpa16(base + (u32)((row * 104 + f * 8) * 2),
                  W2T + (size_t)row * DFF + 96 * c + f * 8);
        }
    };

    // prologue: group1 = [A, W1_0, W2_0]; group2 = [W2_1]
    stage_A(); stage_W1(0); stage_W2(0); CP_COMMIT();
    stage_W2(1); CP_COMMIT();

#pragma unroll 1
    for (int c = 0; c < 8; c++) {
        if (c < 7) { CP_WAIT1(); } else { CP_WAIT0(); }
        __syncthreads();

        // ---- phase A: h-chunk = A @ W1chunk ----
        float acc2[2][3][4] = {};
#pragma unroll
        for (int ks = 0; ks < 12; ks++) {
            const u32 kb = (u32)(ks * 32);
            u32 a[2][4], b[6];
            ldsm_x4(a[0], aqA + kb);
            ldsm_x4(a[1], aqA + (u32)(16 * 200 * 2) + kb);
            ldsm_x4(b, bq4A + kb);
            ldsm_x2(b + 4, bq2A + kb);
#pragma unroll
            for (int i = 0; i < 2; i++) {
                mma16(acc2[i][0], a[i], b);
                mma16(acc2[i][1], a[i], b + 2);
                mma16(acc2[i][2], a[i], b + 4);
            }
        }
        __syncthreads();                       // done reading W1s

        if (c + 1 < 8) { stage_W1(c + 1); CP_COMMIT(); }

        // ---- gelu + store h-chunk to smem (bf16) ----
#pragma unroll
        for (int i = 0; i < 2; i++)
#pragma unroll
            for (int half = 0; half < 2; half++) {
                int row = mwp + i * 16 + g + half * 8;
#pragma unroll
                for (int j = 0; j < 3; j++) {
                    int col = nwA + j * 8 + 2 * tg;
                    int gcol = c * 96 + col;
                    float v0 = acc2[i][j][half * 2 + 0] + __ldg(&b1[gcol]);
                    float v1 = acc2[i][j][half * 2 + 1] + __ldg(&b1[gcol + 1]);
                    *(bf162*)(Hs + row * 104 + col) =
                        __float22bfloat162_rn(make_float2(gelu_f(v0), gelu_f(v1)));
                }
            }
        __syncthreads();
        CP_WAIT2();                            // W2 chunk c resident

        // ---- phase B: out += h @ W2chunk ----
        const u32 w2b = uW2 + (u32)((c & 1) * 19968 * 2);
#pragma unroll
        for (int ks = 0; ks < 6; ks++) {
            const u32 kb = (u32)(ks * 32);
            u32 a[2][4], b[12];
            ldsm_x4(a[0], aqB + kb);
            ldsm_x4(a[1], aqB + (u32)(16 * 104 * 2) + kb);
#pragma unroll
            for (int j2 = 0; j2 < 3; j2++)
                ldsm_x4(b + j2 * 4,
                        w2b + (u32)(((nwB + j2 * 16 + rb) * 104 + kbo) * 2) + kb);
#pragma unroll
            for (int i = 0; i < 2; i++)
#pragma unroll
                for (int jn = 0; jn < 6; jn++)
                    mma16(accB[i][jn], a[i], b + jn * 2);
        }
        __syncthreads();                       // done reading Hs + W2s

        if (c + 2 < 8) { stage_W2(c + 2); CP_COMMIT(); }
    }

    // ---- epilogue: dout = accB + b2 + g_y ----
#pragma unroll
    for (int i = 0; i < 2; i++)
#pragma unroll
        for (int half = 0; half < 2; half++) {
            int m = m0 + mwp + i * 16 + g + half * 8;
#pragma unroll
            for (int jn = 0; jn < 6; jn++) {
                int col = nwB + jn * 8 + 2 * tg;
                const float* yy = g_y + (size_t)m * DIM + col;
                float v0 = accB[i][jn][half * 2 + 0] + __ldg(&b2[col]) + yy[0];
                float v1 = accB[i][jn][half * 2 + 1] + __ldg(&b2[col + 1]) + yy[1];
                *(float2*)(dout + (size_t)m * DIM + col) = make_float2(v0, v1);
            }
        }
}

// ---------------- windowed attention: thread-per-query, packed f32x2 -----
__global__ void __launch_bounds__(64) k_attn(const float* __restrict__ rpb) {
    __shared__ float qs[NTOK][33];
    __shared__ __align__(16) ulonglong2 k2[NTOK][8];
    __shared__ __align__(16) ulonglong2 v2[NTOK][8];
    __shared__ float bs[169];
    __shared__ int rid[NTOK];

    const int bw = blockIdx.x, h = blockIdx.y, t = threadIdx.x;
    const int wdx = bw & 1023, wi = wdx >> 5, wj = wdx & 31;
    const bf16* base = g_qkv + (size_t)bw * NTOK * 576 + h * HD;

    for (int e = t; e < NTOK * 16; e += 64) {
        int n = e >> 4, f = e & 15;
        float2 qv = __bfloat1622float2(*(const bf162*)(base + (size_t)n * 576 + 2 * f));
        qs[n][2 * f] = qv.x; qs[n][2 * f + 1] = qv.y;
    }
    for (int e = t; e < NTOK * 8; e += 64) {
        int n = e >> 3, f = e & 7;
        const bf16* row = base + (size_t)n * 576;
        float2 ka = __bfloat1622float2(*(const bf162*)(row + DIM + 4 * f));
        float2 kb = __bfloat1622float2(*(const bf162*)(row + DIM + 4 * f + 2));
        ulonglong2 kk; kk.x = pk2(ka.x, ka.y); kk.y = pk2(kb.x, kb.y);
        k2[n][f] = kk;
        float2 va = __bfloat1622float2(*(const bf162*)(row + 2 * DIM + 4 * f));
        float2 vb = __bfloat1622float2(*(const bf162*)(row + 2 * DIM + 4 * f + 2));
        ulonglong2 vv; vv.x = pk2(va.x, va.y); vv.y = pk2(vb.x, vb.y);
        v2[n][f] = vv;
    }
    for (int e = t; e < 169; e += 64) bs[e] = rpb[e * NH + h];
    for (int e = t; e < NTOK; e += 64) {
        int r2 = e / WSZ, c2 = e - r2 * WSZ;
        int i2 = wi * WSZ + r2, j2 = wj * WSZ + c2;
        int h2 = (i2 < HWP - WSZ) ? 0 : ((i2 < HWP - SHF) ? 1 : 2);
        int g2 = (j2 < HWP - WSZ) ? 0 : ((j2 < HWP - SHF) ? 1 : 2);
        rid[e] = h2 * 3 + g2;
    }
    __syncthreads();

    if (t >= NTOK) return;

    const int r1 = t / WSZ, c1 = t - r1 * WSZ;
    const int myrid = rid[t];
    const float scale = 0.17677669529663687f;

    u64 q2[16];
#pragma unroll
    for (int f = 0; f < 16; f++) q2[f] = pk2(qs[t][2 * f], qs[t][2 * f + 1]);

    float p[NTOK];
#pragma unroll
    for (int mk = 0; mk < NTOK; mk++) {
        u64 acc0 = 0ull, acc1 = 0ull;
#pragma unroll
        for (int f = 0; f < 8; f++) {
            ulonglong2 kk = k2[mk][f];
            fma2(acc0, q2[2 * f], kk.x);
            fma2(acc1, q2[2 * f + 1], kk.y);
        }
        float2 a0 = unpk2(acc0), a1 = unpk2(acc1);
        float s = (a0.x + a0.y) + (a1.x + a1.y);
        int r2 = mk / WSZ, c2 = mk - r2 * WSZ;
        s = s * scale + bs[(r1 - r2 + 6) * 13 + (c1 - c2 + 6)];
        if (myrid != rid[mk]) s -= 100.f;
        p[mk] = s;
    }

    float mx = -1e30f;
#pragma unroll
    for (int j = 0; j < NTOK; j++) mx = fmaxf(mx, p[j]);
    float sum = 0.f;
#pragma unroll
    for (int j = 0; j < NTOK; j++) { p[j] = __expf(p[j] - mx); sum += p[j]; }
    float inv = 1.f / sum;

    u64 o2[16];
#pragma unroll
    for (int f = 0; f < 16; f++) o2[f] = 0ull;
#pragma unroll
    for (int mk = 0; mk < NTOK; mk++) {
        u64 pm = pk2(p[mk], p[mk]);
#pragma unroll
        for (int f = 0; f < 8; f++) {
            ulonglong2 vv = v2[mk][f];
            fma2(o2[2 * f], pm, vv.x);
            fma2(o2[2 * f + 1], pm, vv.y);
        }
    }
    u32 ob[16];
#pragma unroll
    for (int f = 0; f < 16; f++) {
        float2 ov = unpk2(o2[f]);
        bf162 bb = __float22bfloat162_rn(make_float2(ov.x * inv, ov.y * inv));
        ob[f] = *(u32*)&bb;
    }
    bf16* dst = g_att + ((size_t)(bw * NTOK + t)) * DIM + h * HD;
#pragma unroll
    for (int f = 0; f < 4; f++)
        *(uint4*)(dst + f * 8) = make_uint4(ob[4 * f], ob[4 * f + 1],
                                            ob[4 * f + 2], ob[4 * f + 3]);
}

// ---------------- launcher ----------------
extern "C" void kernel_launch(void* const* d_in, const int* in_sizes, int n_in,
                              void* d_out, int out_size) {
    int base = (n_in >= 16) ? 3 : 1;
    const float* x      = (const float*)d_in[0];
    const float* qkv_w  = (const float*)d_in[base + 0];
    const float* qkv_b  = (const float*)d_in[base + 1];
    const float* proj_w = (const float*)d_in[base + 2];
    const float* proj_b = (const float*)d_in[base + 3];
    const float* rpb    = (const float*)d_in[base + 4];
    const float* n1w    = (const float*)d_in[base + 5];
    const float* n1b    = (const float*)d_in[base + 6];
    const float* n2w    = (const float*)d_in[base + 7];
    const float* n2b    = (const float*)d_in[base + 8];
    const float* w1     = (const float*)d_in[base + 9];
    const float* b1     = (const float*)d_in[base + 10];
    const float* w2     = (const float*)d_in[base + 11];
    const float* b2     = (const float*)d_in[base + 12];
    float* out = (float*)d_out;

    cudaFuncSetAttribute(k_mma<0, 192>, cudaFuncAttributeMaxDynamicSharedMemorySize, MMA_SMEM);
    cudaFuncSetAttribute(k_mma<1, 192>, cudaFuncAttributeMaxDynamicSharedMemorySize, MMA_SMEM);
    cudaFuncSetAttribute(k_mlp, cudaFuncAttributeMaxDynamicSharedMemorySize, MLP_SMEM);

    bf16* g_wt_p;
    cudaGetSymbolAddress((void**)&g_wt_p, g_wt);

    const int nblk_ln = MTOK / 8;
    const int mt = MTOK / 128;         // 3136

    // 0. weight transposes (fp32 -> bf16), single launch
    k_trall<<<1728, 256>>>(qkv_w, proj_w, w1, w2, g_wt_p);
    // 1. LN1 + shifted-window gather -> g_h (bf16)
    k_ln<0><<<nblk_ln, 256>>>(x, n1w, n1b);
    // 2. QKV GEMM -> g_qkv (bf16)
    k_mma<0, 192><<<dim3(6, mt), 256, MMA_SMEM>>>(g_wt_p + WT_QKV, qkv_b, nullptr, nullptr);
    // 3. window attention -> g_att (bf16)
    k_attn<<<dim3(NWTOT, NH), 64>>>(rpb);
    // 4. proj GEMM + reverse roll + residual -> g_y (fp32)
    k_mma<1, 192><<<dim3(2, mt), 256, MMA_SMEM>>>(g_wt_p + WT_PRJ, proj_b, x, nullptr);
    // 5. LN2 -> g_att (bf16)
    k_ln<1><<<nblk_ln, 256>>>(x, n2w, n2b);
    // 6+7. fused MLP (gelu tanh-form) + residual -> d_out
    k_mlp<<<mt, 512, MLP_SMEM>>>(g_wt_p + WT_M1, g_wt_p + WT_M2, b1, b2, out);
}

// round 10
// speedup vs baseline: 4.3096x; 1.0410x over previous
#include <cuda_runtime.h>
#include <cuda_bf16.h>
#include <cuda_fp16.h>
#include <stdint.h>
#include <math.h>

using u32 = unsigned int;
using u64 = unsigned long long;
using bf16 = __nv_bfloat16;
using bf162 = __nv_bfloat162;

// ---------------- problem constants ----------------
constexpr int BATCH = 8;
constexpr int HWP   = 224;
constexpr int LPIX  = HWP * HWP;      // 50176
constexpr int DIM   = 192;
constexpr int NH    = 6;
constexpr int HD    = 32;
constexpr int DFF   = 768;
constexpr int WSZ   = 7;
constexpr int SHF   = 3;
constexpr int NTOK  = 49;
constexpr int NWTOT = 8192;
constexpr int MTOK  = BATCH * LPIX;   // 401408

// ---------------- scratch globals ----------------
__device__ bf16  g_qkv[(size_t)MTOK * 3 * DIM];
__device__ bf16  g_att[(size_t)MTOK * DIM];
__device__ float g_y  [(size_t)MTOK * DIM];       // residual stream (fp32)
__device__ bf16  g_wt [442368];                   // transposed bf16 weights

constexpr int WT_QKV = 0;        // [576][192]
constexpr int WT_PRJ = 110592;   // [192][192]
constexpr int WT_M1  = 147456;   // [768][192]
constexpr int WT_M2  = 294912;   // [192][768]

// g_h: LN1 output (bf16 [MTOK][192])
__device__ bf16  g_h  [(size_t)MTOK * DIM];

// ---------------- PTX helpers ----------------
__device__ __forceinline__ void mma16(float* c, const u32* a, const u32* b) {
    asm volatile(
        "mma.sync.aligned.m16n8k16.row.col.f32.bf16.bf16.f32 "
        "{%0,%1,%2,%3}, {%4,%5,%6,%7}, {%8,%9}, {%0,%1,%2,%3};"
        : "+f"(c[0]), "+f"(c[1]), "+f"(c[2]), "+f"(c[3])
        : "r"(a[0]), "r"(a[1]), "r"(a[2]), "r"(a[3]), "r"(b[0]), "r"(b[1]));
}
__device__ __forceinline__ void ldsm_x4(u32* r, u32 addr) {
    asm volatile("ldmatrix.sync.aligned.m8n8.x4.shared.b16 {%0,%1,%2,%3}, [%4];"
        : "=r"(r[0]), "=r"(r[1]), "=r"(r[2]), "=r"(r[3]) : "r"(addr));
}
__device__ __forceinline__ void ldsm_x2(u32* r, u32 addr) {
    asm volatile("ldmatrix.sync.aligned.m8n8.x2.shared.b16 {%0,%1}, [%2];"
        : "=r"(r[0]), "=r"(r[1]) : "r"(addr));
}
__device__ __forceinline__ u32 smem_u32(const void* p) {
    u32 a; asm("{ .reg .u64 t; cvta.to.shared.u64 t, %1; cvt.u32.u64 %0, t; }" : "=r"(a) : "l"(p));
    return a;
}
__device__ __forceinline__ void cpa16(u32 saddr, const void* gaddr) {
    asm volatile("cp.async.cg.shared.global [%0], [%1], 16;" :: "r"(saddr), "l"(gaddr));
}
#define CP_COMMIT() asm volatile("cp.async.commit_group;" ::: "memory")
#define CP_WAIT2()  asm volatile("cp.async.wait_group 2;" ::: "memory")
#define CP_WAIT1()  asm volatile("cp.async.wait_group 1;" ::: "memory")
#define CP_WAIT0()  asm volatile("cp.async.wait_group 0;" ::: "memory")

// packed f32x2 (FFMA2)
__device__ __forceinline__ u64 pk2(float x, float y) {
    u64 r; asm("mov.b64 %0, {%1,%2};" : "=l"(r) : "f"(x), "f"(y)); return r;
}
__device__ __forceinline__ void fma2(u64& d, u64 a, u64 b) {
    asm("fma.rn.f32x2 %0, %1, %2, %0;" : "+l"(d) : "l"(a), "l"(b));
}
__device__ __forceinline__ float2 unpk2(u64 v) {
    float lo, hi; asm("mov.b64 {%0,%1}, %2;" : "=f"(lo), "=f"(hi) : "l"(v));
    return make_float2(lo, hi);
}

// fast gelu: tanh form (abs err <= ~4e-4, far below bf16 h-rounding)
__device__ __forceinline__ float gelu_f(float v) {
    float u = v * (0.7978845608028654f + 0.035677408136300125f * v * v);
    float th; asm("tanh.approx.f32 %0, %1;" : "=f"(th) : "f"(u));
    return 0.5f * v * (1.f + th);
}

// reverse window-partition + roll(+3): window-order token m -> pixel row base
__device__ __forceinline__ size_t scat_row(int m) {
    int bw = m / NTOK, n = m - bw * NTOK;
    int bb = bw >> 10, wdx = bw & 1023;
    int wi = wdx >> 5, wj = wdx & 31;
    int r = n / WSZ, cc = n - r * WSZ;
    int pi = wi * WSZ + r + SHF; if (pi >= HWP) pi -= HWP;
    int pj = wj * WSZ + cc + SHF; if (pj >= HWP) pj -= HWP;
    return ((size_t)bb * LPIX + (size_t)pi * HWP + pj) * DIM;
}

// ---------------- all weight transposes in one launch --------------------
__global__ void k_trall(const float* __restrict__ qkv_w, const float* __restrict__ proj_w,
                        const float* __restrict__ w1, const float* __restrict__ w2,
                        bf16* __restrict__ wt) {
    int i = blockIdx.x * 256 + threadIdx.x;
    if (i < 110592) {
        int k = i / 576, n = i - k * 576;
        wt[WT_QKV + n * 192 + k] = __float2bfloat16(qkv_w[i]);
    } else if (i < 147456) {
        int j = i - 110592; int k = j / 192, n = j - k * 192;
        wt[WT_PRJ + n * 192 + k] = __float2bfloat16(proj_w[j]);
    } else if (i < 294912) {
        int j = i - 147456; int k = j / 768, n = j - k * 768;
        wt[WT_M1 + n * 192 + k] = __float2bfloat16(w1[j]);
    } else if (i < 442368) {
        int j = i - 294912; int k = j / 192, n = j - k * 192;
        wt[WT_M2 + n * 768 + k] = __float2bfloat16(w2[j]);
    }
}

// ---------------- LayerNorm (one warp / token), bf16 outputs ----------
template <int PHASE>
__global__ void __launch_bounds__(256) k_ln(const float* __restrict__ xin,
                                            const float* __restrict__ w,
                                            const float* __restrict__ b) {
    int warp = threadIdx.x >> 5, lane = threadIdx.x & 31;
    int m = blockIdx.x * 8 + warp;
    const float* src;
    bf16* dst;
    if (PHASE == 0) {
        int bw = m / NTOK, n = m - bw * NTOK;
        int bb = bw >> 10, wdx = bw & 1023;
        int wi = wdx >> 5, wj = wdx & 31;
        int r = n / WSZ, c = n - r * WSZ;
        int pi = wi * WSZ + r + SHF; if (pi >= HWP) pi -= HWP;
        int pj = wj * WSZ + c + SHF; if (pj >= HWP) pj -= HWP;
        src = xin + ((size_t)bb * LPIX + (size_t)pi * HWP + pj) * DIM;
        dst = g_h + (size_t)m * DIM;
    } else {
        src = g_y + (size_t)m * DIM;
        dst = g_att + (size_t)m * DIM;
    }
    float v[6]; float s = 0.f, s2 = 0.f;
#pragma unroll
    for (int j = 0; j < 6; j++) {
        v[j] = src[lane + 32 * j];
        s += v[j]; s2 += v[j] * v[j];
    }
#pragma unroll
    for (int o = 16; o > 0; o >>= 1) {
        s  += __shfl_xor_sync(0xffffffffu, s,  o);
        s2 += __shfl_xor_sync(0xffffffffu, s2, o);
    }
    float mu  = s * (1.f / DIM);
    float var = s2 * (1.f / DIM) - mu * mu;
    float rs  = rsqrtf(var + 1e-5f);
#pragma unroll
    for (int j = 0; j < 6; j++) {
        int kk = lane + 32 * j;
        dst[kk] = __float2bfloat16((v[j] - mu) * rs * __ldg(&w[kk]) + __ldg(&b[kk]));
    }
}

// ---------------- bf16 mma.sync GEMM, ldmatrix + ring-3 cp.async ---------
constexpr int PITCH2 = 200;
constexpr int MMA_SMEM = (128 + 96) * PITCH2 * 2;   // 89,600 B

template <int MODE, int KTOT>
__global__ void __launch_bounds__(256, 2) k_mma(const bf16* __restrict__ WT,
                                                const float* __restrict__ bias,
                                                const float* __restrict__ aux,
                                                float* __restrict__ dout) {
    extern __shared__ bf16 smb[];
    bf16* As = smb;                      // [128][200]
    bf16* Bs = smb + 128 * PITCH2;       // [96][200]

    const int t = threadIdx.x;
    const int n0 = blockIdx.x * 96;
    const int m0 = blockIdx.y * 128;
    const bf16* A = (MODE == 0) ? g_h : g_att;

    const int lane = t & 31, w = t >> 5;
    const int mw = (w >> 2) * 64;
    const int nw = (w & 3) * 24;
    const int g = lane >> 2, tg = lane & 3;

    const u32 uA = smem_u32(As), uB = smem_u32(Bs);
    const u32 aq  = uA + (u32)(((mw + (lane & 15)) * PITCH2 + (lane >> 4) * 8) * 2);
    const int rb  = ((lane >> 4) << 3) + (lane & 7);
    const int kbo = ((lane >> 3) & 1) * 8;
    const u32 bq4 = uB + (u32)(((nw + rb) * PITCH2 + kbo) * 2);
    const u32 bq2 = uB + (u32)(((nw + 16 + rb) * PITCH2 + kbo) * 2);

    float acc[4][3][4] = {};

    constexpr int NSUB = KTOT / 64;

    auto stage = [&](int s) {
        const int col = (s % 3) * 64;
#pragma unroll
        for (int it = 0; it < 7; it++) {
            int id = t + it * 256;
            if (id < 1024) {
                int row = id >> 3, f = id & 7;
                cpa16(uA + (u32)((row * PITCH2 + col + f * 8) * 2),
                      A + (size_t)(m0 + row) * KTOT + s * 64 + f * 8);
            } else {
                int id2 = id - 1024;
                int row = id2 >> 3, f = id2 & 7;
                cpa16(uB + (u32)((row * PITCH2 + col + f * 8) * 2),
                      WT + (size_t)(n0 + row) * KTOT + s * 64 + f * 8);
            }
        }
        CP_COMMIT();
    };

    stage(0);
    if (NSUB > 1) stage(1);
    if (NSUB > 2) stage(2);

#pragma unroll 1
    for (int s = 0; s < NSUB; s++) {
        int rem = NSUB - 1 - s;
        if (rem >= 2) { CP_WAIT2(); } else if (rem == 1) { CP_WAIT1(); } else { CP_WAIT0(); }
        __syncthreads();
        const int koff = (s % 3) * 64;
#pragma unroll
        for (int ks = 0; ks < 4; ks++) {
            const u32 kb2 = (u32)((koff + ks * 16) * 2);
            u32 a[4][4], b[6];
#pragma unroll
            for (int i = 0; i < 4; i++)
                ldsm_x4(a[i], aq + (u32)(i * 16 * PITCH2 * 2) + kb2);
            ldsm_x4(b, bq4 + kb2);
            ldsm_x2(b + 4, bq2 + kb2);
#pragma unroll
            for (int i = 0; i < 4; i++) {
                mma16(acc[i][0], a[i], b);
                mma16(acc[i][1], a[i], b + 2);
                mma16(acc[i][2], a[i], b + 4);
            }
        }
        __syncthreads();
        if (s + 3 < NSUB) stage(s + 3);
    }

#pragma unroll
    for (int i = 0; i < 4; i++) {
        int r0 = m0 + mw + i * 16 + g;
#pragma unroll
        for (int half = 0; half < 2; half++) {
            int m = r0 + half * 8;
            size_t srow;
            if (MODE == 1) srow = scat_row(m);
#pragma unroll
            for (int j = 0; j < 3; j++) {
                int col = n0 + nw + j * 8 + 2 * tg;
                float v0 = acc[i][j][half * 2 + 0] + __ldg(&bias[col]);
                float v1 = acc[i][j][half * 2 + 1] + __ldg(&bias[col + 1]);
                if (MODE == 0) {
                    *(bf162*)(g_qkv + (size_t)m * 576 + col) =
                        __float22bfloat162_rn(make_float2(v0, v1));
                } else {
                    float2 xr = *(const float2*)(aux + srow + col);
                    *(float2*)(g_y + srow + col) = make_float2(xr.x + v0, xr.y + v1);
                }
            }
        }
    }
}

// ---------------- fused MLP: out = gelu(LN2x @ W1 + b1) @ W2 + b2 + g_y ---
constexpr int MLP_SMEM = 196096;   // bytes

__global__ void __launch_bounds__(512, 1) k_mlp(const bf16* __restrict__ W1T,
                                                const bf16* __restrict__ W2T,
                                                const float* __restrict__ b1,
                                                const float* __restrict__ b2,
                                                float* __restrict__ dout) {
    extern __shared__ bf16 smb[];
    bf16* Asm = smb;                 // [128][200]
    bf16* Hs  = smb + 25600;         // [128][104]
    bf16* W1s = smb + 38912;         // [96][200]
    bf16* W2s = smb + 58112;         // [2][192][104]

    const int t = threadIdx.x;
    const int m0 = blockIdx.x * 128;
    const int lane = t & 31, w = t >> 5;
    const int mwp = (w >> 2) * 32;
    const int nwA = (w & 3) * 24;
    const int nwB = (w & 3) * 48;
    const int g = lane >> 2, tg = lane & 3;

    const u32 uA = smem_u32(Asm), uH = smem_u32(Hs);
    const u32 uW1 = smem_u32(W1s), uW2 = smem_u32(W2s);

    const u32 aqA = uA + (u32)(((mwp + (lane & 15)) * 200 + (lane >> 4) * 8) * 2);
    const u32 aqB = uH + (u32)(((mwp + (lane & 15)) * 104 + (lane >> 4) * 8) * 2);
    const int rb  = ((lane >> 4) << 3) + (lane & 7);
    const int kbo = ((lane >> 3) & 1) * 8;
    const u32 bq4A = uW1 + (u32)(((nwA + rb) * 200 + kbo) * 2);
    const u32 bq2A = uW1 + (u32)(((nwA + 16 + rb) * 200 + kbo) * 2);

    float accB[2][6][4] = {};

    auto stage_A = [&] {
        for (int id = t; id < 3072; id += 512) {
            int row = id / 24, f = id - row * 24;
            cpa16(uA + (u32)((row * 200 + f * 8) * 2),
                  g_att + (size_t)(m0 + row) * DIM + f * 8);
        }
    };
    auto stage_W1 = [&](int c) {
        for (int id = t; id < 2304; id += 512) {
            int row = id / 24, f = id - row * 24;
            cpa16(uW1 + (u32)((row * 200 + f * 8) * 2),
                  W1T + (size_t)(96 * c + row) * DIM + f * 8);
        }
    };
    auto stage_W2 = [&](int c) {
        const u32 base = uW2 + (u32)((c & 1) * 19968 * 2);
        for (int id = t; id < 2304; id += 512) {
            int row = id / 12, f = id - row * 12;
            cpa16(base + (u32)((row * 104 + f * 8) * 2),
                  W2T + (size_t)row * DFF + 96 * c + f * 8);
        }
    };

    stage_A(); stage_W1(0); stage_W2(0); CP_COMMIT();
    stage_W2(1); CP_COMMIT();

#pragma unroll 1
    for (int c = 0; c < 8; c++) {
        if (c < 7) { CP_WAIT1(); } else { CP_WAIT0(); }
        __syncthreads();

        float acc2[2][3][4] = {};
#pragma unroll
        for (int ks = 0; ks < 12; ks++) {
            const u32 kb = (u32)(ks * 32);
            u32 a[2][4], b[6];
            ldsm_x4(a[0], aqA + kb);
            ldsm_x4(a[1], aqA + (u32)(16 * 200 * 2) + kb);
            ldsm_x4(b, bq4A + kb);
            ldsm_x2(b + 4, bq2A + kb);
#pragma unroll
            for (int i = 0; i < 2; i++) {
                mma16(acc2[i][0], a[i], b);
                mma16(acc2[i][1], a[i], b + 2);
                mma16(acc2[i][2], a[i], b + 4);
            }
        }
        __syncthreads();

        if (c + 1 < 8) { stage_W1(c + 1); CP_COMMIT(); }

#pragma unroll
        for (int i = 0; i < 2; i++)
#pragma unroll
            for (int half = 0; half < 2; half++) {
                int row = mwp + i * 16 + g + half * 8;
#pragma unroll
                for (int j = 0; j < 3; j++) {
                    int col = nwA + j * 8 + 2 * tg;
                    int gcol = c * 96 + col;
                    float v0 = acc2[i][j][half * 2 + 0] + __ldg(&b1[gcol]);
                    float v1 = acc2[i][j][half * 2 + 1] + __ldg(&b1[gcol + 1]);
                    *(bf162*)(Hs + row * 104 + col) =
                        __float22bfloat162_rn(make_float2(gelu_f(v0), gelu_f(v1)));
                }
            }
        __syncthreads();
        CP_WAIT2();

        const u32 w2b = uW2 + (u32)((c & 1) * 19968 * 2);
#pragma unroll
        for (int ks = 0; ks < 6; ks++) {
            const u32 kb = (u32)(ks * 32);
            u32 a[2][4], b[12];
            ldsm_x4(a[0], aqB + kb);
            ldsm_x4(a[1], aqB + (u32)(16 * 104 * 2) + kb);
#pragma unroll
            for (int j2 = 0; j2 < 3; j2++)
                ldsm_x4(b + j2 * 4,
                        w2b + (u32)(((nwB + j2 * 16 + rb) * 104 + kbo) * 2) + kb);
#pragma unroll
            for (int i = 0; i < 2; i++)
#pragma unroll
                for (int jn = 0; jn < 6; jn++)
                    mma16(accB[i][jn], a[i], b + jn * 2);
        }
        __syncthreads();

        if (c + 2 < 8) { stage_W2(c + 2); CP_COMMIT(); }
    }

#pragma unroll
    for (int i = 0; i < 2; i++)
#pragma unroll
        for (int half = 0; half < 2; half++) {
            int m = m0 + mwp + i * 16 + g + half * 8;
#pragma unroll
            for (int jn = 0; jn < 6; jn++) {
                int col = nwB + jn * 8 + 2 * tg;
                const float* yy = g_y + (size_t)m * DIM + col;
                float v0 = accB[i][jn][half * 2 + 0] + __ldg(&b2[col]) + yy[0];
                float v1 = accB[i][jn][half * 2 + 1] + __ldg(&b2[col + 1]) + yy[1];
                *(float2*)(dout + (size_t)m * DIM + col) = make_float2(v0, v1);
            }
        }
}

// ---------------- windowed attention: fp16-packed probs, high occupancy ---
// One thread per query. Probs packed half2 (25 regs). No max-subtraction
// (scores tiny; mask -> exp(-100) -> 0). K/V padded to 50 rows (row 49 = 0).
__global__ void __launch_bounds__(64, 12) k_attn(const float* __restrict__ rpb) {
    __shared__ __align__(16) ulonglong2 k2[50][8];   // f32x2-packed K rows
    __shared__ __align__(16) ulonglong2 v2[50][8];   // f32x2-packed V rows
    __shared__ float bs[169];
    __shared__ int rid[NTOK];

    const int bw = blockIdx.x, h = blockIdx.y, t = threadIdx.x;
    const int wdx = bw & 1023, wi = wdx >> 5, wj = wdx & 31;
    const bf16* base = g_qkv + (size_t)bw * NTOK * 576 + h * HD;

    // K/V rows -> packed f32x2 quads (row 49 zeroed)
    for (int e = t; e < 50 * 8; e += 64) {
        int n = e >> 3, f = e & 7;
        if (n < NTOK) {
            const bf16* row = base + (size_t)n * 576;
            float2 ka = __bfloat1622float2(*(const bf162*)(row + DIM + 4 * f));
            float2 kb = __bfloat1622float2(*(const bf162*)(row + DIM + 4 * f + 2));
            ulonglong2 kk; kk.x = pk2(ka.x, ka.y); kk.y = pk2(kb.x, kb.y);
            k2[n][f] = kk;
            float2 va = __bfloat1622float2(*(const bf162*)(row + 2 * DIM + 4 * f));
            float2 vb = __bfloat1622float2(*(const bf162*)(row + 2 * DIM + 4 * f + 2));
            ulonglong2 vv; vv.x = pk2(va.x, va.y); vv.y = pk2(vb.x, vb.y);
            v2[n][f] = vv;
        } else {
            ulonglong2 z; z.x = 0ull; z.y = 0ull;
            k2[n][f] = z; v2[n][f] = z;
        }
    }
    for (int e = t; e < 169; e += 64) bs[e] = rpb[e * NH + h];
    for (int e = t; e < NTOK; e += 64) {
        int r2 = e / WSZ, c2 = e - r2 * WSZ;
        int i2 = wi * WSZ + r2, j2 = wj * WSZ + c2;
        int h2 = (i2 < HWP - WSZ) ? 0 : ((i2 < HWP - SHF) ? 1 : 2);
        int g2 = (j2 < HWP - WSZ) ? 0 : ((j2 < HWP - SHF) ? 1 : 2);
        rid[e] = h2 * 3 + g2;
    }
    __syncthreads();

    if (t >= NTOK) return;

    const int r1 = t / WSZ, c1 = t - r1 * WSZ;
    const int myrid = rid[t];
    const float scale = 0.17677669529663687f;

    // q row direct from global, packed to f32x2
    u64 q2[16];
#pragma unroll
    for (int ch = 0; ch < 4; ch++) {
        uint4 qv = *(const uint4*)(base + (size_t)t * 576 + ch * 8);
        u32 ws[4] = {qv.x, qv.y, qv.z, qv.w};
#pragma unroll
        for (int j = 0; j < 4; j++) {
            float2 f = __bfloat1622float2(*(const bf162*)&ws[j]);
            q2[ch * 4 + j] = pk2(f.x, f.y);
        }
    }

    // pass 1: scores -> exp -> packed half2 probs + running sum
    float sum = 0.f;
    u32 ph[25];
#pragma unroll
    for (int jj = 0; jj < 25; jj++) {
        float e01[2];
#pragma unroll
        for (int half = 0; half < 2; half++) {
            int mk = 2 * jj + half;
            if (mk >= NTOK) { e01[half] = 0.f; continue; }
            u64 acc0 = 0ull, acc1 = 0ull;
#pragma unroll
            for (int f = 0; f < 8; f++) {
                ulonglong2 kk = k2[mk][f];                 // broadcast LDS.128
                fma2(acc0, q2[2 * f], kk.x);
                fma2(acc1, q2[2 * f + 1], kk.y);
            }
            float2 a0 = unpk2(acc0), a1 = unpk2(acc1);
            float s = (a0.x + a0.y) + (a1.x + a1.y);
            int r2 = mk / WSZ, c2 = mk - r2 * WSZ;
            s = s * scale + bs[(r1 - r2 + 6) * 13 + (c1 - c2 + 6)];
            if (myrid != rid[mk]) s -= 100.f;
            e01[half] = __expf(s);
        }
        sum += e01[0] + e01[1];
        half2 hh = __floats2half2_rn(e01[0], e01[1]);
        ph[jj] = *(const u32*)&hh;
    }
    const float inv = 1.f / sum;

    // pass 2: AV with packed probs
    u64 o2[16];
#pragma unroll
    for (int f = 0; f < 16; f++) o2[f] = 0ull;
#pragma unroll
    for (int jj = 0; jj < 25; jj++) {
        float2 pp = __half22float2(*(const half2*)&ph[jj]);
        u64 pm0 = pk2(pp.x, pp.x);
        u64 pm1 = pk2(pp.y, pp.y);
        int mk0 = 2 * jj, mk1 = 2 * jj + 1;     // mk1=49 hits zeroed row
#pragma unroll
        for (int f = 0; f < 8; f++) {
            ulonglong2 v0 = v2[mk0][f];
            fma2(o2[2 * f], pm0, v0.x);
            fma2(o2[2 * f + 1], pm0, v0.y);
        }
#pragma unroll
        for (int f = 0; f < 8; f++) {
            ulonglong2 v1 = v2[mk1][f];
            fma2(o2[2 * f], pm1, v1.x);
            fma2(o2[2 * f + 1], pm1, v1.y);
        }
    }
    u32 ob[16];
#pragma unroll
    for (int f = 0; f < 16; f++) {
        float2 ov = unpk2(o2[f]);
        bf162 bb = __float22bfloat162_rn(make_float2(ov.x * inv, ov.y * inv));
        ob[f] = *(const u32*)&bb;
    }
    bf16* dst = g_att + ((size_t)(bw * NTOK + t)) * DIM + h * HD;
#pragma unroll
    for (int f = 0; f < 4; f++)
        *(uint4*)(dst + f * 8) = make_uint4(ob[4 * f], ob[4 * f + 1],
                                            ob[4 * f + 2], ob[4 * f + 3]);
}

// ---------------- launcher ----------------
extern "C" void kernel_launch(void* const* d_in, const int* in_sizes, int n_in,
                              void* d_out, int out_size) {
    int base = (n_in >= 16) ? 3 : 1;
    const float* x      = (const float*)d_in[0];
    const float* qkv_w  = (const float*)d_in[base + 0];
    const float* qkv_b  = (const float*)d_in[base + 1];
    const float* proj_w = (const float*)d_in[base + 2];
    const float* proj_b = (const float*)d_in[base + 3];
    const float* rpb    = (const float*)d_in[base + 4];
    const float* n1w    = (const float*)d_in[base + 5];
    const float* n1b    = (const float*)d_in[base + 6];
    const float* n2w    = (const float*)d_in[base + 7];
    const float* n2b    = (const float*)d_in[base + 8];
    const float* w1     = (const float*)d_in[base + 9];
    const float* b1     = (const float*)d_in[base + 10];
    const float* w2     = (const float*)d_in[base + 11];
    const float* b2     = (const float*)d_in[base + 12];
    float* out = (float*)d_out;

    cudaFuncSetAttribute(k_mma<0, 192>, cudaFuncAttributeMaxDynamicSharedMemorySize, MMA_SMEM);
    cudaFuncSetAttribute(k_mma<1, 192>, cudaFuncAttributeMaxDynamicSharedMemorySize, MMA_SMEM);
    cudaFuncSetAttribute(k_mlp, cudaFuncAttributeMaxDynamicSharedMemorySize, MLP_SMEM);

    bf16* g_wt_p;
    cudaGetSymbolAddress((void**)&g_wt_p, g_wt);

    const int nblk_ln = MTOK / 8;
    const int mt = MTOK / 128;         // 3136

    // 0. weight transposes (fp32 -> bf16), single launch
    k_trall<<<1728, 256>>>(qkv_w, proj_w, w1, w2, g_wt_p);
    // 1. LN1 + shifted-window gather -> g_h (bf16)
    k_ln<0><<<nblk_ln, 256>>>(x, n1w, n1b);
    // 2. QKV GEMM -> g_qkv (bf16)
    k_mma<0, 192><<<dim3(6, mt), 256, MMA_SMEM>>>(g_wt_p + WT_QKV, qkv_b, nullptr, nullptr);
    // 3. window attention -> g_att (bf16)
    k_attn<<<dim3(NWTOT, NH), 64>>>(rpb);
    // 4. proj GEMM + reverse roll + residual -> g_y (fp32)
    k_mma<1, 192><<<dim3(2, mt), 256, MMA_SMEM>>>(g_wt_p + WT_PRJ, proj_b, x, nullptr);
    // 5. LN2 -> g_att (bf16)
    k_ln<1><<<nblk_ln, 256>>>(x, n2w, n2b);
    // 6+7. fused MLP (gelu tanh-form) + residual -> d_out
    k_mlp<<<mt, 512, MLP_SMEM>>>(g_wt_p + WT_M1, g_wt_p + WT_M2, b1, b2, out);
}

// round 11
// speedup vs baseline: 4.8619x; 1.1281x over previous
#include <cuda_runtime.h>
#include <cuda_bf16.h>
#include <cuda_fp16.h>
#include <stdint.h>
#include <math.h>

using u32 = unsigned int;
using u64 = unsigned long long;
using bf16 = __nv_bfloat16;
using bf162 = __nv_bfloat162;

// ---------------- problem constants ----------------
constexpr int BATCH = 8;
constexpr int HWP   = 224;
constexpr int LPIX  = HWP * HWP;      // 50176
constexpr int DIM   = 192;
constexpr int NH    = 6;
constexpr int HD    = 32;
constexpr int DFF   = 768;
constexpr int WSZ   = 7;
constexpr int SHF   = 3;
constexpr int NTOK  = 49;
constexpr int NWTOT = 8192;
constexpr int MTOK  = BATCH * LPIX;   // 401408

// ---------------- scratch globals ----------------
__device__ bf16  g_qkv[(size_t)MTOK * 3 * DIM];
__device__ bf16  g_att[(size_t)MTOK * DIM];
__device__ float g_y  [(size_t)MTOK * DIM];       // residual stream (fp32)
__device__ bf16  g_wt [442368];                   // transposed bf16 weights
__device__ float g_bias[4 * 6 * 64 * 56];         // bias+mask per window type

constexpr int WT_QKV = 0;        // [576][192]
constexpr int WT_PRJ = 110592;   // [192][192]
constexpr int WT_M1  = 147456;   // [768][192]
constexpr int WT_M2  = 294912;   // [192][768]

// g_h: LN1 output (bf16 [MTOK][192])
__device__ bf16  g_h  [(size_t)MTOK * DIM];

// ---------------- PTX helpers ----------------
__device__ __forceinline__ void mma16(float* c, const u32* a, const u32* b) {
    asm volatile(
        "mma.sync.aligned.m16n8k16.row.col.f32.bf16.bf16.f32 "
        "{%0,%1,%2,%3}, {%4,%5,%6,%7}, {%8,%9}, {%0,%1,%2,%3};"
        : "+f"(c[0]), "+f"(c[1]), "+f"(c[2]), "+f"(c[3])
        : "r"(a[0]), "r"(a[1]), "r"(a[2]), "r"(a[3]), "r"(b[0]), "r"(b[1]));
}
__device__ __forceinline__ void mma16h(float* c, const u32* a, const u32* b) {
    asm volatile(
        "mma.sync.aligned.m16n8k16.row.col.f32.f16.f16.f32 "
        "{%0,%1,%2,%3}, {%4,%5,%6,%7}, {%8,%9}, {%0,%1,%2,%3};"
        : "+f"(c[0]), "+f"(c[1]), "+f"(c[2]), "+f"(c[3])
        : "r"(a[0]), "r"(a[1]), "r"(a[2]), "r"(a[3]), "r"(b[0]), "r"(b[1]));
}
__device__ __forceinline__ void ldsm_x4(u32* r, u32 addr) {
    asm volatile("ldmatrix.sync.aligned.m8n8.x4.shared.b16 {%0,%1,%2,%3}, [%4];"
        : "=r"(r[0]), "=r"(r[1]), "=r"(r[2]), "=r"(r[3]) : "r"(addr));
}
__device__ __forceinline__ void ldsm_x2(u32* r, u32 addr) {
    asm volatile("ldmatrix.sync.aligned.m8n8.x2.shared.b16 {%0,%1}, [%2];"
        : "=r"(r[0]), "=r"(r[1]) : "r"(addr));
}
__device__ __forceinline__ u32 smem_u32(const void* p) {
    u32 a; asm("{ .reg .u64 t; cvta.to.shared.u64 t, %1; cvt.u32.u64 %0, t; }" : "=r"(a) : "l"(p));
    return a;
}
__device__ __forceinline__ void cpa16(u32 saddr, const void* gaddr) {
    asm volatile("cp.async.cg.shared.global [%0], [%1], 16;" :: "r"(saddr), "l"(gaddr));
}
#define CP_COMMIT() asm volatile("cp.async.commit_group;" ::: "memory")
#define CP_WAIT2()  asm volatile("cp.async.wait_group 2;" ::: "memory")
#define CP_WAIT1()  asm volatile("cp.async.wait_group 1;" ::: "memory")
#define CP_WAIT0()  asm volatile("cp.async.wait_group 0;" ::: "memory")

// fast gelu: tanh form
__device__ __forceinline__ float gelu_f(float v) {
    float u = v * (0.7978845608028654f + 0.035677408136300125f * v * v);
    float th; asm("tanh.approx.f32 %0, %1;" : "=f"(th) : "f"(u));
    return 0.5f * v * (1.f + th);
}

// reverse window-partition + roll(+3)
__device__ __forceinline__ size_t scat_row(int m) {
    int bw = m / NTOK, n = m - bw * NTOK;
    int bb = bw >> 10, wdx = bw & 1023;
    int wi = wdx >> 5, wj = wdx & 31;
    int r = n / WSZ, cc = n - r * WSZ;
    int pi = wi * WSZ + r + SHF; if (pi >= HWP) pi -= HWP;
    int pj = wj * WSZ + cc + SHF; if (pj >= HWP) pj -= HWP;
    return ((size_t)bb * LPIX + (size_t)pi * HWP + pj) * DIM;
}

// ---------------- all weight transposes in one launch --------------------
__global__ void k_trall(const float* __restrict__ qkv_w, const float* __restrict__ proj_w,
                        const float* __restrict__ w1, const float* __restrict__ w2,
                        bf16* __restrict__ wt) {
    int i = blockIdx.x * 256 + threadIdx.x;
    if (i < 110592) {
        int k = i / 576, n = i - k * 576;
        wt[WT_QKV + n * 192 + k] = __float2bfloat16(qkv_w[i]);
    } else if (i < 147456) {
        int j = i - 110592; int k = j / 192, n = j - k * 192;
        wt[WT_PRJ + n * 192 + k] = __float2bfloat16(proj_w[j]);
    } else if (i < 294912) {
        int j = i - 147456; int k = j / 768, n = j - k * 768;
        wt[WT_M1 + n * 192 + k] = __float2bfloat16(w1[j]);
    } else if (i < 442368) {
        int j = i - 294912; int k = j / 192, n = j - k * 192;
        wt[WT_M2 + n * 768 + k] = __float2bfloat16(w2[j]);
    }
}

// ---------------- bias+mask tables: [type][head][64][56] -----------------
// type: bit1 = bottom-edge window (wi==31), bit0 = right-edge (wj==31).
// pads (m>=49 or n>=49) = -1e30 so exp -> 0.
__global__ void k_bias(const float* __restrict__ rpb) {
    int idx = blockIdx.x * 256 + threadIdx.x;
    if (idx >= 4 * 6 * 64 * 56) return;
    int n  = idx % 56;
    int m  = (idx / 56) % 64;
    int h  = (idx / (56 * 64)) % 6;
    int tt = idx / (56 * 64 * 6);
    float v;
    if (m >= NTOK || n >= NTOK) {
        v = -1e30f;
    } else {
        int rm = m / WSZ, cm = m % WSZ, rn = n / WSZ, cn = n % WSZ;
        v = rpb[((rm - rn + 6) * 13 + (cm - cn + 6)) * NH + h];
        int bi = tt >> 1, bj = tt & 1;
        int hrm = bi ? (rm < 4 ? 1 : 2) : 0;
        int hrn = bi ? (rn < 4 ? 1 : 2) : 0;
        int gcm = bj ? (cm < 4 ? 1 : 2) : 0;
        int gcn = bj ? (cn < 4 ? 1 : 2) : 0;
        if (hrm != hrn || gcm != gcn) v -= 100.f;
    }
    g_bias[idx] = v;
}

// ---------------- LayerNorm (one warp / token), bf16 outputs ----------
template <int PHASE>
__global__ void __launch_bounds__(256) k_ln(const float* __restrict__ xin,
                                            const float* __restrict__ w,
                                            const float* __restrict__ b) {
    int warp = threadIdx.x >> 5, lane = threadIdx.x & 31;
    int m = blockIdx.x * 8 + warp;
    const float* src;
    bf16* dst;
    if (PHASE == 0) {
        int bw = m / NTOK, n = m - bw * NTOK;
        int bb = bw >> 10, wdx = bw & 1023;
        int wi = wdx >> 5, wj = wdx & 31;
        int r = n / WSZ, c = n - r * WSZ;
        int pi = wi * WSZ + r + SHF; if (pi >= HWP) pi -= HWP;
        int pj = wj * WSZ + c + SHF; if (pj >= HWP) pj -= HWP;
        src = xin + ((size_t)bb * LPIX + (size_t)pi * HWP + pj) * DIM;
        dst = g_h + (size_t)m * DIM;
    } else {
        src = g_y + (size_t)m * DIM;
        dst = g_att + (size_t)m * DIM;
    }
    float v[6]; float s = 0.f, s2 = 0.f;
#pragma unroll
    for (int j = 0; j < 6; j++) {
        v[j] = src[lane + 32 * j];
        s += v[j]; s2 += v[j] * v[j];
    }
#pragma unroll
    for (int o = 16; o > 0; o >>= 1) {
        s  += __shfl_xor_sync(0xffffffffu, s,  o);
        s2 += __shfl_xor_sync(0xffffffffu, s2, o);
    }
    float mu  = s * (1.f / DIM);
    float var = s2 * (1.f / DIM) - mu * mu;
    float rs  = rsqrtf(var + 1e-5f);
#pragma unroll
    for (int j = 0; j < 6; j++) {
        int kk = lane + 32 * j;
        dst[kk] = __float2bfloat16((v[j] - mu) * rs * __ldg(&w[kk]) + __ldg(&b[kk]));
    }
}

// ---------------- bf16 mma.sync GEMM, ldmatrix + ring-3 cp.async ---------
constexpr int PITCH2 = 200;
constexpr int MMA_SMEM = (128 + 96) * PITCH2 * 2;   // 89,600 B

template <int MODE, int KTOT>
__global__ void __launch_bounds__(256, 2) k_mma(const bf16* __restrict__ WT,
                                                const float* __restrict__ bias,
                                                const float* __restrict__ aux,
                                                float* __restrict__ dout) {
    extern __shared__ bf16 smb[];
    bf16* As = smb;                      // [128][200]
    bf16* Bs = smb + 128 * PITCH2;       // [96][200]

    const int t = threadIdx.x;
    const int n0 = blockIdx.x * 96;
    const int m0 = blockIdx.y * 128;
    const bf16* A = (MODE == 0) ? g_h : g_att;

    const int lane = t & 31, w = t >> 5;
    const int mw = (w >> 2) * 64;
    const int nw = (w & 3) * 24;
    const int g = lane >> 2, tg = lane & 3;

    const u32 uA = smem_u32(As), uB = smem_u32(Bs);
    const u32 aq  = uA + (u32)(((mw + (lane & 15)) * PITCH2 + (lane >> 4) * 8) * 2);
    const int rb  = ((lane >> 4) << 3) + (lane & 7);
    const int kbo = ((lane >> 3) & 1) * 8;
    const u32 bq4 = uB + (u32)(((nw + rb) * PITCH2 + kbo) * 2);
    const u32 bq2 = uB + (u32)(((nw + 16 + rb) * PITCH2 + kbo) * 2);

    float acc[4][3][4] = {};

    constexpr int NSUB = KTOT / 64;

    auto stage = [&](int s) {
        const int col = (s % 3) * 64;
#pragma unroll
        for (int it = 0; it < 7; it++) {
            int id = t + it * 256;
            if (id < 1024) {
                int row = id >> 3, f = id & 7;
                cpa16(uA + (u32)((row * PITCH2 + col + f * 8) * 2),
                      A + (size_t)(m0 + row) * KTOT + s * 64 + f * 8);
            } else {
                int id2 = id - 1024;
                int row = id2 >> 3, f = id2 & 7;
                cpa16(uB + (u32)((row * PITCH2 + col + f * 8) * 2),
                      WT + (size_t)(n0 + row) * KTOT + s * 64 + f * 8);
            }
        }
        CP_COMMIT();
    };

    stage(0);
    if (NSUB > 1) stage(1);
    if (NSUB > 2) stage(2);

#pragma unroll 1
    for (int s = 0; s < NSUB; s++) {
        int rem = NSUB - 1 - s;
        if (rem >= 2) { CP_WAIT2(); } else if (rem == 1) { CP_WAIT1(); } else { CP_WAIT0(); }
        __syncthreads();
        const int koff = (s % 3) * 64;
#pragma unroll
        for (int ks = 0; ks < 4; ks++) {
            const u32 kb2 = (u32)((koff + ks * 16) * 2);
            u32 a[4][4], b[6];
#pragma unroll
            for (int i = 0; i < 4; i++)
                ldsm_x4(a[i], aq + (u32)(i * 16 * PITCH2 * 2) + kb2);
            ldsm_x4(b, bq4 + kb2);
            ldsm_x2(b + 4, bq2 + kb2);
#pragma unroll
            for (int i = 0; i < 4; i++) {
                mma16(acc[i][0], a[i], b);
                mma16(acc[i][1], a[i], b + 2);
                mma16(acc[i][2], a[i], b + 4);
            }
        }
        __syncthreads();
        if (s + 3 < NSUB) stage(s + 3);
    }

#pragma unroll
    for (int i = 0; i < 4; i++) {
        int r0 = m0 + mw + i * 16 + g;
#pragma unroll
        for (int half = 0; half < 2; half++) {
            int m = r0 + half * 8;
            size_t srow;
            if (MODE == 1) srow = scat_row(m);
#pragma unroll
            for (int j = 0; j < 3; j++) {
                int col = n0 + nw + j * 8 + 2 * tg;
                float v0 = acc[i][j][half * 2 + 0] + __ldg(&bias[col]);
                float v1 = acc[i][j][half * 2 + 1] + __ldg(&bias[col + 1]);
                if (MODE == 0) {
                    *(bf162*)(g_qkv + (size_t)m * 576 + col) =
                        __float22bfloat162_rn(make_float2(v0, v1));
                } else {
                    float2 xr = *(const float2*)(aux + srow + col);
                    *(float2*)(g_y + srow + col) = make_float2(xr.x + v0, xr.y + v1);
                }
            }
        }
    }
}

// ---------------- fused MLP ----------------
constexpr int MLP_SMEM = 196096;   // bytes

__global__ void __launch_bounds__(512, 1) k_mlp(const bf16* __restrict__ W1T,
                                                const bf16* __restrict__ W2T,
                                                const float* __restrict__ b1,
                                                const float* __restrict__ b2,
                                                float* __restrict__ dout) {
    extern __shared__ bf16 smb[];
    bf16* Asm = smb;                 // [128][200]
    bf16* Hs  = smb + 25600;         // [128][104]
    bf16* W1s = smb + 38912;         // [96][200]
    bf16* W2s = smb + 58112;         // [2][192][104]

    const int t = threadIdx.x;
    const int m0 = blockIdx.x * 128;
    const int lane = t & 31, w = t >> 5;
    const int mwp = (w >> 2) * 32;
    const int nwA = (w & 3) * 24;
    const int nwB = (w & 3) * 48;
    const int g = lane >> 2, tg = lane & 3;

    const u32 uA = smem_u32(Asm), uH = smem_u32(Hs);
    const u32 uW1 = smem_u32(W1s), uW2 = smem_u32(W2s);

    const u32 aqA = uA + (u32)(((mwp + (lane & 15)) * 200 + (lane >> 4) * 8) * 2);
    const u32 aqB = uH + (u32)(((mwp + (lane & 15)) * 104 + (lane >> 4) * 8) * 2);
    const int rb  = ((lane >> 4) << 3) + (lane & 7);
    const int kbo = ((lane >> 3) & 1) * 8;
    const u32 bq4A = uW1 + (u32)(((nwA + rb) * 200 + kbo) * 2);
    const u32 bq2A = uW1 + (u32)(((nwA + 16 + rb) * 200 + kbo) * 2);

    float accB[2][6][4] = {};

    auto stage_A = [&] {
        for (int id = t; id < 3072; id += 512) {
            int row = id / 24, f = id - row * 24;
            cpa16(uA + (u32)((row * 200 + f * 8) * 2),
                  g_att + (size_t)(m0 + row) * DIM + f * 8);
        }
    };
    auto stage_W1 = [&](int c) {
        for (int id = t; id < 2304; id += 512) {
            int row = id / 24, f = id - row * 24;
            cpa16(uW1 + (u32)((row * 200 + f * 8) * 2),
                  W1T + (size_t)(96 * c + row) * DIM + f * 8);
        }
    };
    auto stage_W2 = [&](int c) {
        const u32 base = uW2 + (u32)((c & 1) * 19968 * 2);
        for (int id = t; id < 2304; id += 512) {
            int row = id / 12, f = id - row * 12;
            cpa16(base + (u32)((row * 104 + f * 8) * 2),
                  W2T + (size_t)row * DFF + 96 * c + f * 8);
        }
    };

    stage_A(); stage_W1(0); stage_W2(0); CP_COMMIT();
    stage_W2(1); CP_COMMIT();

#pragma unroll 1
    for (int c = 0; c < 8; c++) {
        if (c < 7) { CP_WAIT1(); } else { CP_WAIT0(); }
        __syncthreads();

        float acc2[2][3][4] = {};
#pragma unroll
        for (int ks = 0; ks < 12; ks++) {
            const u32 kb = (u32)(ks * 32);
            u32 a[2][4], b[6];
            ldsm_x4(a[0], aqA + kb);
            ldsm_x4(a[1], aqA + (u32)(16 * 200 * 2) + kb);
            ldsm_x4(b, bq4A + kb);
            ldsm_x2(b + 4, bq2A + kb);
#pragma unroll
            for (int i = 0; i < 2; i++) {
                mma16(acc2[i][0], a[i], b);
                mma16(acc2[i][1], a[i], b + 2);
                mma16(acc2[i][2], a[i], b + 4);
            }
        }
        __syncthreads();

        if (c + 1 < 8) { stage_W1(c + 1); CP_COMMIT(); }

#pragma unroll
        for (int i = 0; i < 2; i++)
#pragma unroll
            for (int half = 0; half < 2; half++) {
                int row = mwp + i * 16 + g + half * 8;
#pragma unroll
                for (int j = 0; j < 3; j++) {
                    int col = nwA + j * 8 + 2 * tg;
                    int gcol = c * 96 + col;
                    float v0 = acc2[i][j][half * 2 + 0] + __ldg(&b1[gcol]);
                    float v1 = acc2[i][j][half * 2 + 1] + __ldg(&b1[gcol + 1]);
                    *(bf162*)(Hs + row * 104 + col) =
                        __float22bfloat162_rn(make_float2(gelu_f(v0), gelu_f(v1)));
                }
            }
        __syncthreads();
        CP_WAIT2();

        const u32 w2b = uW2 + (u32)((c & 1) * 19968 * 2);
#pragma unroll
        for (int ks = 0; ks < 6; ks++) {
            const u32 kb = (u32)(ks * 32);
            u32 a[2][4], b[12];
            ldsm_x4(a[0], aqB + kb);
            ldsm_x4(a[1], aqB + (u32)(16 * 104 * 2) + kb);
#pragma unroll
            for (int j2 = 0; j2 < 3; j2++)
                ldsm_x4(b + j2 * 4,
                        w2b + (u32)(((nwB + j2 * 16 + rb) * 104 + kbo) * 2) + kb);
#pragma unroll
            for (int i = 0; i < 2; i++)
#pragma unroll
                for (int jn = 0; jn < 6; jn++)
                    mma16(accB[i][jn], a[i], b + jn * 2);
        }
        __syncthreads();

        if (c + 2 < 8) { stage_W2(c + 2); CP_COMMIT(); }
    }

#pragma unroll
    for (int i = 0; i < 2; i++)
#pragma unroll
        for (int half = 0; half < 2; half++) {
            int m = m0 + mwp + i * 16 + g + half * 8;
#pragma unroll
            for (int jn = 0; jn < 6; jn++) {
                int col = nwB + jn * 8 + 2 * tg;
                const float* yy = g_y + (size_t)m * DIM + col;
                float v0 = accB[i][jn][half * 2 + 0] + __ldg(&b2[col]) + yy[0];
                float v1 = accB[i][jn][half * 2 + 1] + __ldg(&b2[col + 1]) + yy[1];
                *(float2*)(dout + (size_t)m * DIM + col) = make_float2(v0, v1);
            }
        }
}

// ---------------- tensor-core windowed attention -------------------------
// One block per window, 384 threads = 12 warps = 2 warps x 6 heads.
// Per head: S = Q K^T (m16n8k16 bf16, M=64 pad, N=56 pad, K=32);
// softmax in fragments (bias+mask via precomputed g_bias, pads -> exp 0);
// P->fp16 A-frags in registers (C-layout == A-layout trick); O = P V via
// f16 MMA against transposed V (pitch 72, conflict-free ldmatrix).
// smem (bf16 units): Q[6][64][40] @0, K[6][56][40] @15360, Vt(half)[6][32][72] @28800
constexpr int ATT_SMEM = 85248;

__global__ void __launch_bounds__(384) k_attn() {
    extern __shared__ bf16 smb[];
    bf16*  Qs  = smb;
    bf16*  Ks  = smb + 15360;
    __half* Vts = (__half*)(smb + 28800);

    const int bw = blockIdx.x, t = threadIdx.x;
    const int wdx = bw & 1023, wi = wdx >> 5, wj = wdx & 31;
    const int tt = ((wi == 31) ? 2 : 0) + ((wj == 31) ? 1 : 0);
    const float* Tb = g_bias + tt * (6 * 64 * 56);
    const bf16* base = g_qkv + (size_t)bw * NTOK * 576;

    // zero smem (pads must be 0)
    for (int i = t; i < ATT_SMEM / 16; i += 384)
        ((uint4*)smb)[i] = make_uint4(0, 0, 0, 0);
    __syncthreads();

    const u32 uQ = smem_u32(Qs), uK = smem_u32(Ks), uVt = smem_u32(Vts);

    // Q,K via cp.async (4 x 16B per row per head)
    for (int e = t; e < 1176; e += 384) {
        int f = e & 3, tok = (e >> 2) % 49, h = e / 196;
        cpa16(uQ + (u32)(((h * 64 + tok) * 40 + f * 8) * 2),
              base + (size_t)tok * 576 + h * 32 + f * 8);
        cpa16(uK + (u32)(((h * 56 + tok) * 40 + f * 8) * 2),
              base + (size_t)tok * 576 + 192 + h * 32 + f * 8);
    }
    CP_COMMIT();
    // V transposed -> fp16
    for (int e = t; e < 4704; e += 384) {
        int f = e & 15, tok = (e >> 4) % 49, h = e / 784;
        float2 v = __bfloat1622float2(*(const bf162*)(base + (size_t)tok * 576 + 384 + h * 32 + 2 * f));
        Vts[(h * 32 + 2 * f) * 72 + tok]     = __float2half(v.x);
        Vts[(h * 32 + 2 * f + 1) * 72 + tok] = __float2half(v.y);
    }
    CP_WAIT0();
    __syncthreads();

    const int lane = t & 31, w = t >> 5;
    const int h = w >> 1;
    const int mbase = (w & 1) * 32;
    const int g = lane >> 2, tg = lane & 3;
    const int rb = ((lane >> 4) << 3) + (lane & 7);
    const int kbo = ((lane >> 3) & 1) * 8;

    // ---- S = Q K^T ----
    float S[2][7][4] = {};
    const u32 aQ = uQ + (u32)(((h * 64 + mbase + (lane & 15)) * 40 + (lane >> 4) * 8) * 2);
    const u32 bK = uK + (u32)(((h * 56 + rb) * 40 + kbo) * 2);
#pragma unroll
    for (int ks = 0; ks < 2; ks++) {
        const u32 ko = (u32)(ks * 32);
        u32 a[2][4], b[14];
        ldsm_x4(a[0], aQ + ko);
        ldsm_x4(a[1], aQ + (u32)(16 * 40 * 2) + ko);
        ldsm_x4(b,      bK + ko);
        ldsm_x4(b + 4,  bK + (u32)(16 * 40 * 2) + ko);
        ldsm_x4(b + 8,  bK + (u32)(32 * 40 * 2) + ko);
        ldsm_x2(b + 12, bK + (u32)(48 * 40 * 2) + ko);
#pragma unroll
        for (int i = 0; i < 2; i++)
#pragma unroll
            for (int j = 0; j < 7; j++)
                mma16(S[i][j], a[i], b + 2 * j);
    }

    // ---- softmax (no max-sub; bias/mask/pads from g_bias) ----
    const float scale = 0.17677669529663687f;
    float rinv[2][2];
#pragma unroll
    for (int i = 0; i < 2; i++) {
        float rs0 = 0.f, rs1 = 0.f;
#pragma unroll
        for (int j = 0; j < 7; j++) {
            int n = 8 * j + 2 * tg;
            int m0r = mbase + 16 * i + g;
            float2 t0 = __ldg((const float2*)(Tb + (h * 64 + m0r) * 56 + n));
            float2 t1 = __ldg((const float2*)(Tb + (h * 64 + m0r + 8) * 56 + n));
            float e0 = __expf(fmaf(S[i][j][0], scale, t0.x));
            float e1 = __expf(fmaf(S[i][j][1], scale, t0.y));
            float e2 = __expf(fmaf(S[i][j][2], scale, t1.x));
            float e3 = __expf(fmaf(S[i][j][3], scale, t1.y));
            S[i][j][0] = e0; S[i][j][1] = e1; S[i][j][2] = e2; S[i][j][3] = e3;
            rs0 += e0 + e1; rs1 += e2 + e3;
        }
        rs0 += __shfl_xor_sync(0xffffffffu, rs0, 1);
        rs0 += __shfl_xor_sync(0xffffffffu, rs0, 2);
        rs1 += __shfl_xor_sync(0xffffffffu, rs1, 1);
        rs1 += __shfl_xor_sync(0xffffffffu, rs1, 2);
        rinv[i][0] = 1.f / rs0;
        rinv[i][1] = 1.f / rs1;
    }

    // ---- O = P V (P fp16 A-frags straight from registers) ----
    float O[2][4][4] = {};
    const u32 bV = uVt + (u32)(((h * 32 + rb) * 72 + kbo) * 2);
#pragma unroll
    for (int kk = 0; kk < 4; kk++) {
        u32 a[2][4], b[8];
#pragma unroll
        for (int i = 0; i < 2; i++) {
            int j0 = 2 * kk, j1 = 2 * kk + 1;
            half2 h0 = __floats2half2_rn(S[i][j0][0], S[i][j0][1]);
            half2 h1 = __floats2half2_rn(S[i][j0][2], S[i][j0][3]);
            a[i][0] = *(const u32*)&h0;
            a[i][1] = *(const u32*)&h1;
            if (j1 < 7) {
                half2 h2 = __floats2half2_rn(S[i][j1][0], S[i][j1][1]);
                half2 h3 = __floats2half2_rn(S[i][j1][2], S[i][j1][3]);
                a[i][2] = *(const u32*)&h2;
                a[i][3] = *(const u32*)&h3;
            } else {
                a[i][2] = 0u; a[i][3] = 0u;
            }
        }
        const u32 ko = (u32)(kk * 32);
        ldsm_x4(b,     bV + ko);
        ldsm_x4(b + 4, bV + (u32)(16 * 72 * 2) + ko);
#pragma unroll
        for (int i = 0; i < 2; i++)
#pragma unroll
            for (int j = 0; j < 4; j++)
                mma16h(O[i][j], a[i], b + 2 * j);
    }

    // ---- store (normalize by row-sum), rows < 49 only ----
    bf16* dst0 = g_att + (size_t)bw * NTOK * DIM + h * 32;
#pragma unroll
    for (int i = 0; i < 2; i++)
#pragma unroll
        for (int half = 0; half < 2; half++) {
            int m = mbase + 16 * i + g + 8 * half;
            if (m < NTOK) {
                float inv = rinv[i][half];
                bf16* dp = dst0 + (size_t)m * DIM + 2 * tg;
#pragma unroll
                for (int j = 0; j < 4; j++) {
                    bf162 bb = __float22bfloat162_rn(
                        make_float2(O[i][j][2 * half] * inv, O[i][j][2 * half + 1] * inv));
                    *(bf162*)(dp + 8 * j) = bb;
                }
            }
        }
}

// ---------------- launcher ----------------
extern "C" void kernel_launch(void* const* d_in, const int* in_sizes, int n_in,
                              void* d_out, int out_size) {
    int base = (n_in >= 16) ? 3 : 1;
    const float* x      = (const float*)d_in[0];
    const float* qkv_w  = (const float*)d_in[base + 0];
    const float* qkv_b  = (const float*)d_in[base + 1];
    const float* proj_w = (const float*)d_in[base + 2];
    const float* proj_b = (const float*)d_in[base + 3];
    const float* rpb    = (const float*)d_in[base + 4];
    const float* n1w    = (const float*)d_in[base + 5];
    const float* n1b    = (const float*)d_in[base + 6];
    const float* n2w    = (const float*)d_in[base + 7];
    const float* n2b    = (const float*)d_in[base + 8];
    const float* w1     = (const float*)d_in[base + 9];
    const float* b1     = (const float*)d_in[base + 10];
    const float* w2     = (const float*)d_in[base + 11];
    const float* b2     = (const float*)d_in[base + 12];
    float* out = (float*)d_out;

    cudaFuncSetAttribute(k_mma<0, 192>, cudaFuncAttributeMaxDynamicSharedMemorySize, MMA_SMEM);
    cudaFuncSetAttribute(k_mma<1, 192>, cudaFuncAttributeMaxDynamicSharedMemorySize, MMA_SMEM);
    cudaFuncSetAttribute(k_mlp, cudaFuncAttributeMaxDynamicSharedMemorySize, MLP_SMEM);
    cudaFuncSetAttribute(k_attn, cudaFuncAttributeMaxDynamicSharedMemorySize, ATT_SMEM);

    bf16* g_wt_p;
    cudaGetSymbolAddress((void**)&g_wt_p, g_wt);

    const int nblk_ln = MTOK / 8;
    const int mt = MTOK / 128;         // 3136

    // 0. weight transposes + bias/mask tables
    k_trall<<<1728, 256>>>(qkv_w, proj_w, w1, w2, g_wt_p);
    k_bias<<<(4 * 6 * 64 * 56 + 255) / 256, 256>>>(rpb);
    // 1. LN1 + shifted-window gather -> g_h (bf16)
    k_ln<0><<<nblk_ln, 256>>>(x, n1w, n1b);
    // 2. QKV GEMM -> g_qkv (bf16)
    k_mma<0, 192><<<dim3(6, mt), 256, MMA_SMEM>>>(g_wt_p + WT_QKV, qkv_b, nullptr, nullptr);
    // 3. tensor-core window attention -> g_att (bf16)
    k_attn<<<NWTOT, 384, ATT_SMEM>>>();
    // 4. proj GEMM + reverse roll + residual -> g_y (fp32)
    k_mma<1, 192><<<dim3(2, mt), 256, MMA_SMEM>>>(g_wt_p + WT_PRJ, proj_b, x, nullptr);
    // 5. LN2 -> g_att (bf16)
    k_ln<1><<<nblk_ln, 256>>>(x, n2w, n2b);
    // 6+7. fused MLP + residual -> d_out
    k_mlp<<<mt, 512, MLP_SMEM>>>(g_wt_p + WT_M1, g_wt_p + WT_M2, b1, b2, out);
}